// round 6
// baseline (speedup 1.0000x reference)
#include <cuda_runtime.h>

// Problem constants
#define NCTA   128
#define TPB    320
#define NB     512
#define BT     4
#define NC     184
#define HH     32
#define IND    14
#define DD     15
#define NPRED  24
#define NHIST  24
#define NFEAT  13
#define FTOT   48

// Global scratch (per-CTA private slices)
__device__ float g_y0[(size_t)NCTA * NC * BT * HH];
__device__ float g_y1[(size_t)NCTA * NC * BT * HH];
__device__ float g_pre[(size_t)NCTA * NPRED * NC * BT];

// Shared memory layout (float offsets)
#define OFF_X    0        // 184*16*4 = 11776  x tile [c][k16][b]
#define OFF_Y0B  11776    // 184*32*4 = 23552  bwd y0 [c][j][b]
#define OFF_XIN  35328    // 2*2*128  = 512    staged fwd y0 [dir][buf][k][b]
#define OFF_G    35840    // 2*4*128  = 1024   pre-activated gates [dir][b][row]
#define OFF_H    36864    // 4*32*4   = 512    h state [ld][j][b]
#define OFF_XN   37376    // 184*4    = 736
#define OFF_GX   38112    // 384
#define OFF_GH   38496    // 1536
#define OFF_U    40032    // 64
#define SMEM_FLOATS 40096 // 160,384 bytes

typedef unsigned long long u64;

__device__ __forceinline__ u64 pk2(float w) {
    u64 r; asm("mov.b64 %0, {%1, %1};" : "=l"(r) : "f"(w)); return r;
}
__device__ __forceinline__ u64 pack2(float a, float b) {
    u64 r; asm("mov.b64 %0, {%1, %2};" : "=l"(r) : "f"(a), "f"(b)); return r;
}
__device__ __forceinline__ void ffma2(u64& a, u64 x, u64 w) {
    asm("fma.rn.f32x2 %0, %1, %2, %0;" : "+l"(a) : "l"(x), "l"(w));
}
__device__ __forceinline__ u64 addx2(u64 a, u64 b) {
    u64 r; asm("add.rn.f32x2 %0, %1, %2;" : "=l"(r) : "l"(a), "l"(b)); return r;
}
__device__ __forceinline__ float2 unpk(u64 a) {
    float2 f; asm("mov.b64 {%0, %1}, %2;" : "=f"(f.x), "=f"(f.y) : "l"(a)); return f;
}
__device__ __forceinline__ float sigf(float x) {
    return __fdividef(1.0f, 1.0f + __expf(-x));
}
__device__ __forceinline__ float tanhfast(float x) {
    x = fminf(fmaxf(x, -15.0f), 15.0f);
    float e = __expf(2.0f * x);
    return __fdividef(e - 1.0f, e + 1.0f);
}
#define BAR_ARRIVE(id) asm volatile("bar.arrive %0, %1;" :: "r"(id), "r"(160) : "memory")
#define BAR_SYNCN(id)  asm volatile("bar.sync %0, %1;"   :: "r"(id), "r"(160) : "memory")

// ===================== Pre-pass: MLP feature part for all t =====================
#define TPP 736
__global__ void __launch_bounds__(TPP, 1)
pre_mlp_kernel(const float* __restrict__ feature, const float* __restrict__ W_mlp)
{
    __shared__ float ft[2][13 * 96];   // [kk][t24][b4]
    const int tid = threadIdx.x;
    const int cta = blockIdx.x;
    const int bg  = cta * BT;
    const int tg  = tid / NC;          // 0..3 t-group
    const int j   = tid - tg * NC;     // 0..183

    u64 A[6], B[6];
#pragma unroll
    for (int q = 0; q < 6; ++q) { A[q] = 0ULL; B[q] = 0ULL; }

    for (int e = tid; e < 13 * 96; e += TPP) {
        int kk = e / 96, r = e - kk * 96, tt = r >> 2, b = r & 3;
        ft[0][e] = feature[(((size_t)(bg + b) * FTOT + NHIST + tt) * NC + 0) * NFEAT + kk];
    }
    __syncthreads();

    for (int c = 0; c < NC; ++c) {
        const int p = c & 1;
        float pfv[2];
#pragma unroll
        for (int q = 0; q < 2; ++q) {
            int e = tid + q * TPP;
            if (c + 1 < NC && e < 13 * 96) {
                int kk = e / 96, r = e - kk * 96, tt = r >> 2, b = r & 3;
                pfv[q] = feature[(((size_t)(bg + b) * FTOT + NHIST + tt) * NC + (c + 1)) * NFEAT + kk];
            }
        }
        {
            float wv[13];
#pragma unroll
            for (int kk = 0; kk < 13; ++kk)
                wv[kk] = W_mlp[((size_t)c * IND + 1 + kk) * NC + j];
#pragma unroll
            for (int kk = 0; kk < 13; ++kk) {
                u64 w2 = pk2(wv[kk]);
#pragma unroll
                for (int q = 0; q < 6; ++q) {
                    int tt = tg * 6 + q;
                    ulonglong2 f2 = *(const ulonglong2*)&ft[p][kk * 96 + tt * 4];
                    ffma2(A[q], f2.x, w2);
                    ffma2(B[q], f2.y, w2);
                }
            }
        }
#pragma unroll
        for (int q = 0; q < 2; ++q) {
            int e = tid + q * TPP;
            if (c + 1 < NC && e < 13 * 96) ft[p ^ 1][e] = pfv[q];
        }
        __syncthreads();
    }
#pragma unroll
    for (int q = 0; q < 6; ++q) {
        int tt = tg * 6 + q;
        float2 fa = unpk(A[q]), fb = unpk(B[q]);
        *(float4*)&g_pre[(((size_t)cta * NPRED + tt) * NC + j) * 4] =
            make_float4(fa.x, fa.y, fb.x, fb.y);
    }
}

// ===================== Main persistent kernel =====================
__global__ void __launch_bounds__(TPB, 1)
bilstm_kernel(const float* __restrict__ rain_hist,
              const float* __restrict__ feature,
              const float* __restrict__ h0,
              const float* __restrict__ c0,
              const float* __restrict__ W_mlp,
              const float* __restrict__ b_mlp,
              const float* __restrict__ Wih_g,
              const float* __restrict__ Whh_g,
              const float* __restrict__ b_ih_g,
              const float* __restrict__ b_hh_g,
              const float* __restrict__ Wih0,
              const float* __restrict__ Whh0,
              const float* __restrict__ b0,
              const float* __restrict__ Wih1,
              const float* __restrict__ Whh1,
              const float* __restrict__ b1,
              const float* __restrict__ W_fc,
              const float* __restrict__ b_fc,
              float* __restrict__ out)
{
    extern __shared__ float sm[];
    float* sX   = sm + OFF_X;
    float* sY0B = sm + OFF_Y0B;
    float* sXin = sm + OFF_XIN;
    float* sG   = sm + OFF_G;
    float* sH   = sm + OFF_H;
    float* sXN  = sm + OFF_XN;
    float* sGX  = sm + OFF_GX;
    float* sGH  = sm + OFF_GH;
    float* sU   = sm + OFF_U;

    const int tid  = threadIdx.x;
    const int cta  = blockIdx.x;
    const int bg   = cta * BT;
    const int lane = tid & 31;
    const int wid  = tid >> 5;           // 0..9
    const bool isGate = (wid < 8);
    const int dirg = wid >> 2;           // gate: 0/1 (valid for wid<8)
    const int cls  = wid & 3;            // gate class: 0=i,1=f,2=g,3=o
    const int jg   = cls * 32 + lane;    // gate row within dir
    const int dA   = wid - 8;            // aux: dir (wid 8,9)
    const int jA   = lane;

    // ---- gate-warp weights in registers ----
    float w0x[DD], w0h[HH], w1f[HH], w1b[HH], w1h[HH], bias0 = 0.f, bias1 = 0.f;
    if (isGate) {
        const int gr = dirg * 128 + jg;
#pragma unroll
        for (int k = 0; k < DD; ++k) w0x[k] = Wih0[gr * DD + k];
#pragma unroll
        for (int k = 0; k < HH; ++k) w0h[k] = Whh0[gr * HH + k];
        bias0 = b0[gr];
#pragma unroll
        for (int k = 0; k < HH; ++k) w1f[k] = Wih1[gr * 64 + k];
#pragma unroll
        for (int k = 0; k < HH; ++k) w1b[k] = Wih1[gr * 64 + 32 + k];
#pragma unroll
        for (int k = 0; k < HH; ++k) w1h[k] = Whh1[gr * HH + k];
        bias1 = b1[gr];
    }
    // ---- aux-warp c-state in registers (persists across all t) ----
    float c0r[4], c1r[4];
    if (!isGate) {
#pragma unroll
        for (int b = 0; b < 4; ++b) {
            c0r[b] = c0[((size_t)dA * NB + bg + b) * HH + jA];
            c1r[b] = c0[((size_t)(2 + dA) * NB + bg + b) * HH + jA];
        }
    }

    // ---- initial h, xn ----
    for (int e = tid; e < 4 * HH * BT; e += TPB) {
        int ld = e >> 7, k = (e >> 2) & 31, b = e & 3;
        sH[(ld * HH + k) * BT + b] = h0[((size_t)ld * NB + bg + b) * HH + k];
    }
    for (int e = tid; e < NC * BT; e += TPB) {
        int c = e >> 2, b = e & 3;
        sXN[c * BT + b] = rain_hist[((size_t)(bg + b) * NHIST + (NHIST - 1)) * NC + c];
    }
    __syncthreads();

    for (int t = 0; t < NPRED; ++t) {
        // ============ Phase 1: build x tile ============
        for (int e = tid; e < NC * NFEAT * BT; e += TPB) {
            int b = e / (NC * NFEAT);
            int rem = e - b * (NC * NFEAT);
            int c = rem / NFEAT;
            int kk = rem - c * NFEAT;
            sX[(c * 16 + 2 + kk) * BT + b] =
                feature[(((size_t)(bg + b) * FTOT + NHIST + t) * NC + c) * NFEAT + kk];
        }
        for (int e = tid; e < NC * BT; e += TPB) {
            int c = e >> 2, b = e & 3;
            sX[(c * 16 + 1) * BT + b] = sXN[c * BT + b];
        }
        __syncthreads();

        // ============ Phase 2: MLP = precomputed feat part + xn part ============
        if (tid < NC) {
            const int j = tid;
            float4 pre4 = *(const float4*)(g_pre + (((size_t)cta * NPRED + t) * NC + j) * 4);
            u64 A[4], B[4];
            A[0] = pack2(pre4.x, pre4.y); B[0] = pack2(pre4.z, pre4.w);
#pragma unroll
            for (int q = 1; q < 4; ++q) { A[q] = 0ULL; B[q] = 0ULL; }
            for (int c = 0; c < NC; c += 4) {
#pragma unroll
                for (int q = 0; q < 4; ++q) {
                    float w = W_mlp[((size_t)(c + q) * IND) * NC + j];
                    ulonglong2 xv = *(const ulonglong2*)(sXN + (c + q) * 4);
                    u64 w2 = pk2(w);
                    ffma2(A[q], xv.x, w2);
                    ffma2(B[q], xv.y, w2);
                }
            }
            u64 a01 = addx2(addx2(A[0], A[1]), addx2(A[2], A[3]));
            u64 a23 = addx2(addx2(B[0], B[1]), addx2(B[2], B[3]));
            a01 = addx2(a01, pk2(b_mlp[j]));
            a23 = addx2(a23, pk2(b_mlp[j]));
            float2 v01 = unpk(a01), v23 = unpk(a23);
            sX[(j * 16) * BT + 0] = sigf(v01.x);
            sX[(j * 16) * BT + 1] = sigf(v01.y);
            sX[(j * 16) * BT + 2] = sigf(v23.x);
            sX[(j * 16) * BT + 3] = sigf(v23.y);
        }
        __syncthreads();

        // ============ Phase 3: GRU cell ============
        for (int e = tid; e < BT * DD; e += TPB) {
            int b = e / DD, k = e - b * DD;
            float s = 0.0f;
            for (int c = 0; c < NC; ++c) s += sX[(c * 16 + k) * BT + b];
            sU[b * 16 + k] = s * (1.0f / NC);
        }
        __syncthreads();
        for (int e = tid; e < BT * 96; e += TPB) {
            int b = e / 96, j = e - b * 96;
            float a = b_ih_g[j];
#pragma unroll
            for (int k = 0; k < DD; ++k)
                a = fmaf(sU[b * 16 + k], Wih_g[k * 96 + j], a);
            sGX[e] = a;
        }
        for (int e = tid; e < 16 * 96; e += TPB) {
            int lb = e / 96, j = e - lb * 96;
            int l = lb >> 2, b = lb & 3;
            float a = b_hh_g[j];
#pragma unroll
            for (int k = 0; k < HH; ++k)
                a = fmaf(sH[(l * HH + k) * BT + b], Whh_g[k * 96 + j], a);
            sGH[e] = a;
        }
        __syncthreads();
        for (int e = tid; e < 4 * BT * HH; e += TPB) {
            int l = e >> 7, b = (e >> 5) & 3, j = e & 31;
            int gb = b * 96, ghb = (l * BT + b) * 96;
            float r = sigf(sGX[gb + j]      + sGH[ghb + j]);
            float z = sigf(sGX[gb + 32 + j] + sGH[ghb + 32 + j]);
            float n = tanhfast(sGX[gb + 64 + j] + r * sGH[ghb + 64 + j]);
            int hi = (l * HH + j) * BT + b;
            sH[hi] = (1.0f - z) * n + z * sH[hi];
        }
        __syncthreads();

        // ============ Phase 4: BiLSTM layer 0 (warp-specialized ping-pong) ============
        if (isGate) {
            u64 x01, x23;
            {
                int city = dirg ? (NC - 1) : 0;
                const ulonglong2* xp = (const ulonglong2*)(sX + city * 64);
                x01 = pk2(bias0); x23 = x01;
#pragma unroll
                for (int k = 0; k < DD; ++k) {
                    u64 w = pk2(w0x[k]);
                    ulonglong2 xv = xp[k];
                    ffma2(x01, xv.x, w); ffma2(x23, xv.y, w);
                }
            }
            for (int s = 0; s < NC; ++s) {
                const ulonglong2* hp = (const ulonglong2*)(sH + dirg * 128);
                u64 h01a = 0, h23a = 0, h01b = 0, h23b = 0;
#pragma unroll
                for (int k = 0; k < 16; ++k) {
                    u64 w = pk2(w0h[k]);
                    ulonglong2 hv = hp[k];
                    ffma2(h01a, hv.x, w); ffma2(h23a, hv.y, w);
                }
#pragma unroll
                for (int k = 0; k < 16; ++k) {
                    u64 w = pk2(w0h[16 + k]);
                    ulonglong2 hv = hp[16 + k];
                    ffma2(h01b, hv.x, w); ffma2(h23b, hv.y, w);
                }
                float2 v01 = unpk(addx2(x01, addx2(h01a, h01b)));
                float2 v23 = unpk(addx2(x23, addx2(h23a, h23b)));
                float n0, n1, n2, n3;
                if (cls == 2) {
                    n0 = tanhfast(v01.x); n1 = tanhfast(v01.y);
                    n2 = tanhfast(v23.x); n3 = tanhfast(v23.y);
                } else {
                    n0 = sigf(v01.x); n1 = sigf(v01.y);
                    n2 = sigf(v23.x); n3 = sigf(v23.y);
                }
                float* gp = sG + dirg * 512 + jg;
                gp[0] = n0; gp[128] = n1; gp[256] = n2; gp[384] = n3;
                BAR_ARRIVE(1 + dirg);
                if (s + 1 < NC) {
                    int city = dirg ? (NC - 2 - s) : (s + 1);
                    const ulonglong2* xp = (const ulonglong2*)(sX + city * 64);
                    x01 = pk2(bias0); x23 = x01;
#pragma unroll
                    for (int k = 0; k < DD; ++k) {
                        u64 w = pk2(w0x[k]);
                        ulonglong2 xv = xp[k];
                        ffma2(x01, xv.x, w); ffma2(x23, xv.y, w);
                    }
                }
                BAR_SYNCN(3 + dirg);
            }
        } else {
            for (int s = 0; s < NC; ++s) {
                BAR_SYNCN(1 + dA);
                int city = dA ? (NC - 1 - s) : s;
#pragma unroll
                for (int b = 0; b < 4; ++b) {
                    const float* g = sG + dA * 512 + b * 128;
                    float iv = g[jA], fv = g[32 + jA], gv = g[64 + jA], ov = g[96 + jA];
                    c0r[b] = fmaf(fv, c0r[b], iv * gv);
                    float h = ov * tanhfast(c0r[b]);
                    sH[(dA * HH + jA) * BT + b] = h;
                    if (dA == 0)
                        g_y0[((size_t)(cta * NC + city) * BT + b) * HH + jA] = h;
                    else
                        sY0B[city * 128 + jA * 4 + b] = h;
                }
                BAR_ARRIVE(3 + dA);
            }
        }
        __syncthreads();

        // ============ Phase 5: BiLSTM layer 1 ============
        // stage y0f for cities 0,1 per dir
        for (int e = tid; e < 512; e += TPB) {
            int dd = e >> 8, r = e & 255, buf = r >> 7, r2 = r & 127, k = r2 >> 2, b = r2 & 3;
            int city = buf ? (dd ? NC - 2 : 1) : (dd ? NC - 1 : 0);
            sXin[e] = g_y0[((size_t)(cta * NC + city) * BT + b) * HH + k];
        }
        __syncthreads();

        if (isGate) {
            u64 fb01, fb23;
            {
                const ulonglong2* yp = (const ulonglong2*)(sXin + dirg * 256);
                const ulonglong2* bp = (const ulonglong2*)(sY0B + (dirg ? NC - 1 : 0) * 128);
                u64 f01 = pk2(bias1), f23 = f01, bb01 = 0, bb23 = 0;
#pragma unroll
                for (int k = 0; k < HH; ++k) {
                    u64 wf = pk2(w1f[k]), wb = pk2(w1b[k]);
                    ulonglong2 yv = yp[k], bv = bp[k];
                    ffma2(f01, yv.x, wf); ffma2(f23, yv.y, wf);
                    ffma2(bb01, bv.x, wb); ffma2(bb23, bv.y, wb);
                }
                fb01 = addx2(f01, bb01); fb23 = addx2(f23, bb23);
            }
            for (int s = 0; s < NC; ++s) {
                const ulonglong2* hp = (const ulonglong2*)(sH + (2 + dirg) * 128);
                u64 h01a = 0, h23a = 0, h01b = 0, h23b = 0;
#pragma unroll
                for (int k = 0; k < 16; ++k) {
                    u64 w = pk2(w1h[k]);
                    ulonglong2 hv = hp[k];
                    ffma2(h01a, hv.x, w); ffma2(h23a, hv.y, w);
                }
#pragma unroll
                for (int k = 0; k < 16; ++k) {
                    u64 w = pk2(w1h[16 + k]);
                    ulonglong2 hv = hp[16 + k];
                    ffma2(h01b, hv.x, w); ffma2(h23b, hv.y, w);
                }
                float2 v01 = unpk(addx2(fb01, addx2(h01a, h01b)));
                float2 v23 = unpk(addx2(fb23, addx2(h23a, h23b)));
                float n0, n1, n2, n3;
                if (cls == 2) {
                    n0 = tanhfast(v01.x); n1 = tanhfast(v01.y);
                    n2 = tanhfast(v23.x); n3 = tanhfast(v23.y);
                } else {
                    n0 = sigf(v01.x); n1 = sigf(v01.y);
                    n2 = sigf(v23.x); n3 = sigf(v23.y);
                }
                float* gp = sG + dirg * 512 + jg;
                gp[0] = n0; gp[128] = n1; gp[256] = n2; gp[384] = n3;
                BAR_ARRIVE(1 + dirg);
                if (s + 1 < NC) {
                    const ulonglong2* yp = (const ulonglong2*)(sXin + dirg * 256 + ((s + 1) & 1) * 128);
                    int city = dirg ? (NC - 2 - s) : (s + 1);
                    const ulonglong2* bp = (const ulonglong2*)(sY0B + city * 128);
                    u64 f01 = pk2(bias1), f23 = f01, bb01 = 0, bb23 = 0;
#pragma unroll
                    for (int k = 0; k < HH; ++k) {
                        u64 wf = pk2(w1f[k]), wb = pk2(w1b[k]);
                        ulonglong2 yv = yp[k], bv = bp[k];
                        ffma2(f01, yv.x, wf); ffma2(f23, yv.y, wf);
                        ffma2(bb01, bv.x, wb); ffma2(bb23, bv.y, wb);
                    }
                    fb01 = addx2(f01, bb01); fb23 = addx2(f23, bb23);
                }
                BAR_SYNCN(3 + dirg);
            }
        } else {
            float pf[4];
            {
                int cp = dA ? (NC - 3) : 2;
#pragma unroll
                for (int b = 0; b < 4; ++b)
                    pf[b] = g_y0[((size_t)(cta * NC + cp) * BT + b) * HH + jA];
            }
            for (int s = 0; s < NC; ++s) {
                BAR_SYNCN(1 + dA);
                // stash y0f(city s+2) into buf[s&1]
                *(float4*)(sXin + dA * 256 + (s & 1) * 128 + jA * 4) =
                    make_float4(pf[0], pf[1], pf[2], pf[3]);
#pragma unroll
                for (int b = 0; b < 4; ++b) {
                    const float* g = sG + dA * 512 + b * 128;
                    float iv = g[jA], fv = g[32 + jA], gv = g[64 + jA], ov = g[96 + jA];
                    c1r[b] = fmaf(fv, c1r[b], iv * gv);
                    float h = ov * tanhfast(c1r[b]);
                    sH[((2 + dA) * HH + jA) * BT + b] = h;
                    if (dA == 0)
                        g_y1[((size_t)(cta * NC + s) * BT + b) * HH + jA] = h;
                }
                {
                    int cp = s + 3; if (cp > NC - 1) cp = NC - 1;
                    int cc = dA ? (NC - 1 - cp) : cp;
#pragma unroll
                    for (int b = 0; b < 4; ++b)
                        pf[b] = g_y0[((size_t)(cta * NC + cc) * BT + b) * HH + jA];
                }
                BAR_ARRIVE(3 + dA);
            }
        }
        __syncthreads();

        // ============ Phase 6: FC head (parallel) ============
        {
            const float bfc = b_fc[0];
            for (int e = tid; e < NC * BT; e += TPB) {
                int c = e >> 2, b = e & 3;
                const float4* yp = (const float4*)(g_y1 + ((size_t)(cta * NC + c) * BT + b) * HH);
                const float4* wp = (const float4*)W_fc;
                float a = bfc;
#pragma unroll
                for (int q = 0; q < 8; ++q) {
                    float4 y = yp[q], w = wp[q];
                    a = fmaf(y.x, w.x, a); a = fmaf(y.y, w.y, a);
                    a = fmaf(y.z, w.z, a); a = fmaf(y.w, w.w, a);
                }
                sXN[c * BT + b] = a;
                out[((size_t)(bg + b) * NPRED + t) * NC + c] = a;
            }
        }
        __syncthreads();
    }
}

extern "C" void kernel_launch(void* const* d_in, const int* in_sizes, int n_in,
                              void* d_out, int out_size) {
    (void)in_sizes; (void)n_in; (void)out_size;
    const float* rain_hist = (const float*)d_in[0];
    const float* feature   = (const float*)d_in[1];
    const float* h0        = (const float*)d_in[2];
    const float* c0        = (const float*)d_in[3];
    const float* W_mlp     = (const float*)d_in[4];
    const float* b_mlp     = (const float*)d_in[5];
    const float* Wih_g     = (const float*)d_in[6];
    const float* Whh_g     = (const float*)d_in[7];
    const float* b_ih_g    = (const float*)d_in[8];
    const float* b_hh_g    = (const float*)d_in[9];
    const float* Wih0      = (const float*)d_in[10];
    const float* Whh0      = (const float*)d_in[11];
    const float* b0        = (const float*)d_in[12];
    const float* Wih1      = (const float*)d_in[13];
    const float* Whh1      = (const float*)d_in[14];
    const float* b1        = (const float*)d_in[15];
    const float* W_fc      = (const float*)d_in[16];
    const float* b_fc      = (const float*)d_in[17];

    pre_mlp_kernel<<<NCTA, TPP>>>(feature, W_mlp);

    size_t smem = (size_t)SMEM_FLOATS * sizeof(float);
    cudaFuncSetAttribute(bilstm_kernel,
                         cudaFuncAttributeMaxDynamicSharedMemorySize, (int)smem);
    bilstm_kernel<<<NCTA, TPB, smem>>>(
        rain_hist, feature, h0, c0, W_mlp, b_mlp,
        Wih_g, Whh_g, b_ih_g, b_hh_g,
        Wih0, Whh0, b0, Wih1, Whh1, b1,
        W_fc, b_fc, (float*)d_out);
}

// round 7
// speedup vs baseline: 1.6075x; 1.6075x over previous
#include <cuda_runtime.h>

// Problem constants
#define NCTA   128
#define TPB    256
#define NB     512
#define BT     4
#define NC     184
#define HH     32
#define IND    14
#define DD     15
#define NPRED  24
#define NHIST  24
#define NFEAT  13
#define FTOT   48

// Global scratch (per-CTA private slices; same-CTA produce/consume)
__device__ float g_y0[(size_t)NCTA * NC * BT * HH];   // fwd y0
__device__ float g_y1[(size_t)NCTA * NC * BT * HH];   // fwd y1

// Shared memory layout (float offsets)
#define OFF_X    0        // 184*16*4 = 11776  x tile [c][k16][b]
#define OFF_Y0B  11776    // 184*32*4 = 23552  bwd y0 [c][j][b]
#define OFF_XIN  35328    // 2dir*2buf*128     staged fwd y0 [k][b]
#define OFF_G    35840    // 2*4*128  = 1024   pre-activated gates [dir][b][row]
#define OFF_H    36864    // 4*32*4   = 512    h state [ld][j][b]
#define OFF_XN   37376    // 184*4    = 736
#define OFF_GX   38112    // 384
#define OFF_GH   38496    // 1536
#define OFF_U    40032    // 64
#define SMEM_FLOATS 40096 // 160,384 bytes

typedef unsigned long long u64;

__device__ __forceinline__ u64 pk2(float w) {
    u64 r; asm("mov.b64 %0, {%1, %1};" : "=l"(r) : "f"(w)); return r;
}
__device__ __forceinline__ void ffma2(u64& a, u64 x, u64 w) {
    asm("fma.rn.f32x2 %0, %1, %2, %0;" : "+l"(a) : "l"(x), "l"(w));
}
__device__ __forceinline__ u64 addx2(u64 a, u64 b) {
    u64 r; asm("add.rn.f32x2 %0, %1, %2;" : "=l"(r) : "l"(a), "l"(b)); return r;
}
__device__ __forceinline__ float2 unpk(u64 a) {
    float2 f; asm("mov.b64 {%0, %1}, %2;" : "=f"(f.x), "=f"(f.y) : "l"(a)); return f;
}
__device__ __forceinline__ float sigf(float x) {
    return __fdividef(1.0f, 1.0f + __expf(-x));
}
__device__ __forceinline__ float tanhfast(float x) {
    x = fminf(fmaxf(x, -15.0f), 15.0f);
    float e = __expf(2.0f * x);
    return __fdividef(e - 1.0f, e + 1.0f);
}

__global__ void __launch_bounds__(TPB, 1)
bilstm_kernel(const float* __restrict__ rain_hist,
              const float* __restrict__ feature,
              const float* __restrict__ h0,
              const float* __restrict__ c0,
              const float* __restrict__ W_mlp,
              const float* __restrict__ b_mlp,
              const float* __restrict__ Wih_g,
              const float* __restrict__ Whh_g,
              const float* __restrict__ b_ih_g,
              const float* __restrict__ b_hh_g,
              const float* __restrict__ Wih0,
              const float* __restrict__ Whh0,
              const float* __restrict__ b0,
              const float* __restrict__ Wih1,
              const float* __restrict__ Whh1,
              const float* __restrict__ b1,
              const float* __restrict__ W_fc,
              const float* __restrict__ b_fc,
              float* __restrict__ out)
{
    extern __shared__ float sm[];
    float* sX   = sm + OFF_X;
    float* sY0B = sm + OFF_Y0B;
    float* sXin = sm + OFF_XIN;
    float* sG   = sm + OFF_G;
    float* sH   = sm + OFF_H;
    float* sXN  = sm + OFF_XN;
    float* sGX  = sm + OFF_GX;
    float* sGH  = sm + OFF_GH;
    float* sU   = sm + OFF_U;

    const int tid  = threadIdx.x;
    const int cta  = blockIdx.x;
    const int bg   = cta * BT;
    const int dirg = tid >> 7;          // gate-phase direction / update du
    const int jg   = tid & 127;         // gate row within dir
    const int cls  = (tid >> 5) & 3;    // gate class of this row (warp-uniform)
    const int bu   = (tid >> 5) & 3;    // update-phase batch
    const int ju   = tid & 31;          // update-phase hidden idx
    const int row  = dirg * 128 + jg;
    const int loc  = tid & 127;
    const int kst  = loc >> 2, bst = loc & 3;   // staging (k,b)

    // ---- per-thread weight rows in registers ----
    float w0x[DD], w0h[HH], w1f[HH], w1b[HH], w1h[HH], bias0, bias1;
#pragma unroll
    for (int k = 0; k < DD; ++k) w0x[k] = Wih0[row * DD + k];
#pragma unroll
    for (int k = 0; k < HH; ++k) w0h[k] = Whh0[row * HH + k];
    bias0 = b0[row];
#pragma unroll
    for (int k = 0; k < HH; ++k) w1f[k] = Wih1[row * 64 + k];
#pragma unroll
    for (int k = 0; k < HH; ++k) w1b[k] = Wih1[row * 64 + 32 + k];
#pragma unroll
    for (int k = 0; k < HH; ++k) w1h[k] = Whh1[row * HH + k];
    bias1 = b1[row];

    // ---- c-state in registers: this thread owns (dirg, bu, ju) slices ----
    float cL0 = c0[((size_t)dirg * NB + bg + bu) * HH + ju];
    float cL1 = c0[((size_t)(2 + dirg) * NB + bg + bu) * HH + ju];

    // ---- initial h, xn ----
    for (int e = tid; e < 4 * HH * BT; e += TPB) {
        int ld = e >> 7, k = (e >> 2) & 31, b = e & 3;
        sH[(ld * HH + k) * BT + b] = h0[((size_t)ld * NB + bg + b) * HH + k];
    }
    for (int e = tid; e < NC * BT; e += TPB) {
        int c = e >> 2, b = e & 3;
        sXN[c * BT + b] = rain_hist[((size_t)(bg + b) * NHIST + (NHIST - 1)) * NC + c];
    }
    __syncthreads();

    for (int t = 0; t < NPRED; ++t) {
        // ============ Phase 1: build x tile (slot0=g, slot1=xn, 2..14=feat) ============
        for (int e = tid; e < NC * NFEAT * BT; e += TPB) {
            int b = e / (NC * NFEAT);
            int rem = e - b * (NC * NFEAT);
            int c = rem / NFEAT;
            int kk = rem - c * NFEAT;
            sX[(c * 16 + 2 + kk) * BT + b] =
                feature[(((size_t)(bg + b) * FTOT + NHIST + t) * NC + c) * NFEAT + kk];
        }
        for (int e = tid; e < NC * BT; e += TPB) {
            int c = e >> 2, b = e & 3;
            sX[(c * 16 + 1) * BT + b] = sXN[c * BT + b];
        }
        __syncthreads();

        // ============ Phase 2: gated graph MLP (in-loop, 4-way c-split chains) ============
        if (tid < NC) {
            const int j = tid;
            u64 A0 = pk2(b_mlp[j]), A1 = 0, A2 = 0, A3 = 0;
            u64 B0 = A0, B1 = 0, B2 = 0, B3 = 0;
            for (int c = 0; c < NC; c += 4) {
#pragma unroll
                for (int q = 0; q < 4; ++q) {
                    const float* wp = W_mlp + ((size_t)(c + q) * IND) * NC + j;
                    const ulonglong2* xp = (const ulonglong2*)(sX + ((c + q) * 16 + 1) * BT);
#pragma unroll
                    for (int kk = 0; kk < IND; ++kk) {
                        u64 w = pk2(wp[(size_t)kk * NC]);
                        ulonglong2 xv = xp[kk];
                        if (q == 0) { ffma2(A0, xv.x, w); ffma2(B0, xv.y, w); }
                        if (q == 1) { ffma2(A1, xv.x, w); ffma2(B1, xv.y, w); }
                        if (q == 2) { ffma2(A2, xv.x, w); ffma2(B2, xv.y, w); }
                        if (q == 3) { ffma2(A3, xv.x, w); ffma2(B3, xv.y, w); }
                    }
                }
            }
            float2 v01 = unpk(addx2(addx2(A0, A1), addx2(A2, A3)));
            float2 v23 = unpk(addx2(addx2(B0, B1), addx2(B2, B3)));
            sX[(j * 16) * BT + 0] = sigf(v01.x);
            sX[(j * 16) * BT + 1] = sigf(v01.y);
            sX[(j * 16) * BT + 2] = sigf(v23.x);
            sX[(j * 16) * BT + 3] = sigf(v23.y);
        }
        __syncthreads();

        // ============ Phase 3: GRU cell ============
        for (int e = tid; e < BT * DD; e += TPB) {
            int b = e / DD, k = e - b * DD;
            float s = 0.0f;
            for (int c = 0; c < NC; ++c) s += sX[(c * 16 + k) * BT + b];
            sU[b * 16 + k] = s * (1.0f / NC);
        }
        __syncthreads();
        for (int e = tid; e < BT * 96; e += TPB) {
            int b = e / 96, j = e - b * 96;
            float a = b_ih_g[j];
#pragma unroll
            for (int k = 0; k < DD; ++k)
                a = fmaf(sU[b * 16 + k], Wih_g[k * 96 + j], a);
            sGX[e] = a;
        }
        for (int e = tid; e < 16 * 96; e += TPB) {
            int lb = e / 96, j = e - lb * 96;
            int l = lb >> 2, b = lb & 3;
            float a = b_hh_g[j];
#pragma unroll
            for (int k = 0; k < HH; ++k)
                a = fmaf(sH[(l * HH + k) * BT + b], Whh_g[k * 96 + j], a);
            sGH[e] = a;
        }
        __syncthreads();
        for (int e = tid; e < 4 * BT * HH; e += TPB) {
            int l = e >> 7, b = (e >> 5) & 3, j = e & 31;
            int gb = b * 96, ghb = (l * BT + b) * 96;
            float r = sigf(sGX[gb + j]      + sGH[ghb + j]);
            float z = sigf(sGX[gb + 32 + j] + sGH[ghb + 32 + j]);
            float n = tanhfast(sGX[gb + 64 + j] + r * sGH[ghb + 64 + j]);
            int hi = (l * HH + j) * BT + b;
            sH[hi] = (1.0f - z) * n + z * sH[hi];
        }
        __syncthreads();

        // ============ Phase 4: BiLSTM layer 0 ============
        {
            u64 x01, x23;
            {   // x-part prologue s = 0
                int city = dirg ? (NC - 1) : 0;
                const ulonglong2* xp = (const ulonglong2*)(sX + city * 64);
                x01 = pk2(bias0); x23 = x01;
#pragma unroll
                for (int k = 0; k < DD; ++k) {
                    u64 w = pk2(w0x[k]);
                    ulonglong2 xv = xp[k];
                    ffma2(x01, xv.x, w); ffma2(x23, xv.y, w);
                }
            }
            for (int s = 0; s < NC; ++s) {
                // h-part: 2 chains of 16 per output pair
                const ulonglong2* hp = (const ulonglong2*)(sH + dirg * 128);
                u64 hA01 = 0, hA23 = 0, hB01 = 0, hB23 = 0;
#pragma unroll
                for (int k = 0; k < 16; ++k) {
                    u64 w = pk2(w0h[k]);
                    ulonglong2 hv = hp[k];
                    ffma2(hA01, hv.x, w); ffma2(hA23, hv.y, w);
                }
#pragma unroll
                for (int k = 0; k < 16; ++k) {
                    u64 w = pk2(w0h[16 + k]);
                    ulonglong2 hv = hp[16 + k];
                    ffma2(hB01, hv.x, w); ffma2(hB23, hv.y, w);
                }
                float2 v01 = unpk(addx2(x01, addx2(hA01, hB01)));
                float2 v23 = unpk(addx2(x23, addx2(hA23, hB23)));
                float n0, n1, n2, n3;
                if (cls == 2) {
                    n0 = tanhfast(v01.x); n1 = tanhfast(v01.y);
                    n2 = tanhfast(v23.x); n3 = tanhfast(v23.y);
                } else {
                    n0 = sigf(v01.x); n1 = sigf(v01.y);
                    n2 = sigf(v23.x); n3 = sigf(v23.y);
                }
                float* gp = sG + dirg * 512 + jg;
                gp[0] = n0; gp[128] = n1; gp[256] = n2; gp[384] = n3;
                __syncthreads();
                // window: update(s) + x-part(s+1)
                {
                    const float* g = sG + dirg * 512 + bu * 128;
                    float iv = g[ju], fv = g[32 + ju], gv = g[64 + ju], ov = g[96 + ju];
                    cL0 = fmaf(fv, cL0, iv * gv);
                    float h = ov * tanhfast(cL0);
                    sH[(dirg * HH + ju) * BT + bu] = h;
                    int cityu = dirg ? (NC - 1 - s) : s;
                    if (dirg == 0)
                        g_y0[((size_t)(cta * NC + cityu) * BT + bu) * HH + ju] = h;
                    else
                        sY0B[cityu * 128 + ju * 4 + bu] = h;
                }
                if (s + 1 < NC) {
                    int cityn = dirg ? (NC - 2 - s) : (s + 1);
                    const ulonglong2* xp = (const ulonglong2*)(sX + cityn * 64);
                    x01 = pk2(bias0); x23 = x01;
#pragma unroll
                    for (int k = 0; k < DD; ++k) {
                        u64 w = pk2(w0x[k]);
                        ulonglong2 xv = xp[k];
                        ffma2(x01, xv.x, w); ffma2(x23, xv.y, w);
                    }
                }
                __syncthreads();
            }
        }

        // ============ Phase 5: BiLSTM layer 1 ============
        {
            u64 fb01, fb23;
            float pf;
            {   // prologue: stage y0f(0), prefetch y0f(1), y0b-part(0)
                int c0_ = dirg ? (NC - 1) : 0;
                sXin[(dirg * 2 + 0) * 128 + kst * 4 + bst] =
                    g_y0[((size_t)(cta * NC + c0_) * BT + bst) * HH + kst];
                int c1_ = dirg ? (NC - 2) : 1;
                pf = g_y0[((size_t)(cta * NC + c1_) * BT + bst) * HH + kst];
                int city = dirg ? (NC - 1) : 0;
                const ulonglong2* bp2 = (const ulonglong2*)(sY0B + city * 128);
                fb01 = pk2(bias1); fb23 = fb01;
#pragma unroll
                for (int k = 0; k < HH; ++k) {
                    u64 w = pk2(w1b[k]);
                    ulonglong2 bv = bp2[k];
                    ffma2(fb01, bv.x, w); ffma2(fb23, bv.y, w);
                }
            }
            __syncthreads();
            int buf = 0;
            for (int s = 0; s < NC; ++s) {
                // f-part (staged y0f) + h-part: 2+2 chains of 16
                const ulonglong2* fp2 = (const ulonglong2*)(sXin + (dirg * 2 + buf) * 128);
                const ulonglong2* hp  = (const ulonglong2*)(sH + (2 + dirg) * 128);
                u64 fA01 = 0, fA23 = 0, fB01 = 0, fB23 = 0;
                u64 hA01 = 0, hA23 = 0, hB01 = 0, hB23 = 0;
#pragma unroll
                for (int k = 0; k < 16; ++k) {
                    u64 w = pk2(w1f[k]);
                    ulonglong2 yv = fp2[k];
                    ffma2(fA01, yv.x, w); ffma2(fA23, yv.y, w);
                }
#pragma unroll
                for (int k = 0; k < 16; ++k) {
                    u64 w = pk2(w1f[16 + k]);
                    ulonglong2 yv = fp2[16 + k];
                    ffma2(fB01, yv.x, w); ffma2(fB23, yv.y, w);
                }
#pragma unroll
                for (int k = 0; k < 16; ++k) {
                    u64 w = pk2(w1h[k]);
                    ulonglong2 hv = hp[k];
                    ffma2(hA01, hv.x, w); ffma2(hA23, hv.y, w);
                }
#pragma unroll
                for (int k = 0; k < 16; ++k) {
                    u64 w = pk2(w1h[16 + k]);
                    ulonglong2 hv = hp[16 + k];
                    ffma2(hB01, hv.x, w); ffma2(hB23, hv.y, w);
                }
                float2 v01 = unpk(addx2(addx2(fb01, addx2(fA01, fB01)), addx2(hA01, hB01)));
                float2 v23 = unpk(addx2(addx2(fb23, addx2(fA23, fB23)), addx2(hA23, hB23)));
                float n0, n1, n2, n3;
                if (cls == 2) {
                    n0 = tanhfast(v01.x); n1 = tanhfast(v01.y);
                    n2 = tanhfast(v23.x); n3 = tanhfast(v23.y);
                } else {
                    n0 = sigf(v01.x); n1 = sigf(v01.y);
                    n2 = sigf(v23.x); n3 = sigf(v23.y);
                }
                float* gp = sG + dirg * 512 + jg;
                gp[0] = n0; gp[128] = n1; gp[256] = n2; gp[384] = n3;
                __syncthreads();
                // window: stash y0f(s+1), prefetch y0f(s+2), update(s), y0b-part(s+1)
                if (s + 1 < NC)
                    sXin[(dirg * 2 + (buf ^ 1)) * 128 + kst * 4 + bst] = pf;
                if (s + 2 < NC) {
                    int cp = dirg ? (NC - 3 - s) : (s + 2);
                    pf = g_y0[((size_t)(cta * NC + cp) * BT + bst) * HH + kst];
                }
                {
                    const float* g = sG + dirg * 512 + bu * 128;
                    float iv = g[ju], fv = g[32 + ju], gv = g[64 + ju], ov = g[96 + ju];
                    cL1 = fmaf(fv, cL1, iv * gv);
                    float h = ov * tanhfast(cL1);
                    sH[((2 + dirg) * HH + ju) * BT + bu] = h;
                    if (dirg == 0)
                        g_y1[((size_t)(cta * NC + s) * BT + bu) * HH + ju] = h;
                }
                if (s + 1 < NC) {
                    int cityn = dirg ? (NC - 2 - s) : (s + 1);
                    const ulonglong2* bp2 = (const ulonglong2*)(sY0B + cityn * 128);
                    fb01 = pk2(bias1); fb23 = fb01;
#pragma unroll
                    for (int k = 0; k < HH; ++k) {
                        u64 w = pk2(w1b[k]);
                        ulonglong2 bv = bp2[k];
                        ffma2(fb01, bv.x, w); ffma2(fb23, bv.y, w);
                    }
                }
                __syncthreads();
                buf ^= 1;
            }
        }

        // ============ Phase 6: FC head (parallel epilogue) ============
        {
            const float bfc = b_fc[0];
            for (int e = tid; e < NC * BT; e += TPB) {
                int c = e >> 2, b = e & 3;
                const float4* yp = (const float4*)(g_y1 + ((size_t)(cta * NC + c) * BT + b) * HH);
                const float4* wp = (const float4*)W_fc;
                float a = bfc;
#pragma unroll
                for (int q = 0; q < 8; ++q) {
                    float4 y = yp[q], w = wp[q];
                    a = fmaf(y.x, w.x, a); a = fmaf(y.y, w.y, a);
                    a = fmaf(y.z, w.z, a); a = fmaf(y.w, w.w, a);
                }
                sXN[c * BT + b] = a;
                out[((size_t)(bg + b) * NPRED + t) * NC + c] = a;
            }
        }
        __syncthreads();
    }
}

extern "C" void kernel_launch(void* const* d_in, const int* in_sizes, int n_in,
                              void* d_out, int out_size) {
    (void)in_sizes; (void)n_in; (void)out_size;
    const float* rain_hist = (const float*)d_in[0];
    const float* feature   = (const float*)d_in[1];
    const float* h0        = (const float*)d_in[2];
    const float* c0        = (const float*)d_in[3];
    const float* W_mlp     = (const float*)d_in[4];
    const float* b_mlp     = (const float*)d_in[5];
    const float* Wih_g     = (const float*)d_in[6];
    const float* Whh_g     = (const float*)d_in[7];
    const float* b_ih_g    = (const float*)d_in[8];
    const float* b_hh_g    = (const float*)d_in[9];
    const float* Wih0      = (const float*)d_in[10];
    const float* Whh0      = (const float*)d_in[11];
    const float* b0        = (const float*)d_in[12];
    const float* Wih1      = (const float*)d_in[13];
    const float* Whh1      = (const float*)d_in[14];
    const float* b1        = (const float*)d_in[15];
    const float* W_fc      = (const float*)d_in[16];
    const float* b_fc      = (const float*)d_in[17];

    size_t smem = (size_t)SMEM_FLOATS * sizeof(float);
    cudaFuncSetAttribute(bilstm_kernel,
                         cudaFuncAttributeMaxDynamicSharedMemorySize, (int)smem);
    bilstm_kernel<<<NCTA, TPB, smem>>>(
        rain_hist, feature, h0, c0, W_mlp, b_mlp,
        Wih_g, Whh_g, b_ih_g, b_hh_g,
        Wih0, Whh0, b0, Wih1, Whh1, b1,
        W_fc, b_fc, (float*)d_out);
}

// round 8
// speedup vs baseline: 1.6123x; 1.0030x over previous
#include <cuda_runtime.h>

// Problem constants
#define NCTA   128
#define TPB    256
#define NB     512
#define BT     4
#define NC     184
#define HH     32
#define IND    14
#define DD     15
#define NPRED  24
#define NHIST  24
#define NFEAT  13
#define FTOT   48

// Global scratch (per-CTA private slices; same-CTA produce/consume)
__device__ float g_y0[(size_t)NCTA * NC * BT * HH];   // fwd y0, [city][j][b]
__device__ float g_y1[(size_t)NCTA * NC * BT * HH];   // fwd y1, [city][j][b]

// Shared memory layout (float offsets)
#define OFF_X    0        // 184*16*4 = 11776  x tile [c][k16][b]
#define OFF_Y0B  11776    // 184*32*4 = 23552  bwd y0 [c][j][b]
#define OFF_XIN  35328    // 2dir*2buf*128     staged fwd y0 [k][b]
#define OFF_H    35840    // 2buf*4ld*32*4=1024 h state
#define OFF_XN   36864    // 184*4 = 736
#define OFF_GX   37600    // 384
#define OFF_GH   37984    // 1536
#define OFF_U    39520    // 64
#define SMEM_FLOATS 39584 // 158,336 bytes

typedef unsigned long long u64;

__device__ __forceinline__ u64 pk2(float w) {
    u64 r; asm("mov.b64 %0, {%1, %1};" : "=l"(r) : "f"(w)); return r;
}
__device__ __forceinline__ void ffma2(u64& a, u64 x, u64 w) {
    asm("fma.rn.f32x2 %0, %1, %2, %0;" : "+l"(a) : "l"(x), "l"(w));
}
__device__ __forceinline__ u64 addx2(u64 a, u64 b) {
    u64 r; asm("add.rn.f32x2 %0, %1, %2;" : "=l"(r) : "l"(a), "l"(b)); return r;
}
__device__ __forceinline__ float2 unpk(u64 a) {
    float2 f; asm("mov.b64 {%0, %1}, %2;" : "=f"(f.x), "=f"(f.y) : "l"(a)); return f;
}
__device__ __forceinline__ float sigf(float x) {
    return __fdividef(1.0f, 1.0f + __expf(-x));
}
__device__ __forceinline__ float tanhfast(float x) {
    x = fminf(fmaxf(x, -15.0f), 15.0f);
    float e = __expf(2.0f * x);
    return __fdividef(e - 1.0f, e + 1.0f);
}

__global__ void __launch_bounds__(TPB, 1)
bilstm_kernel(const float* __restrict__ rain_hist,
              const float* __restrict__ feature,
              const float* __restrict__ h0,
              const float* __restrict__ c0,
              const float* __restrict__ W_mlp,
              const float* __restrict__ b_mlp,
              const float* __restrict__ Wih_g,
              const float* __restrict__ Whh_g,
              const float* __restrict__ b_ih_g,
              const float* __restrict__ b_hh_g,
              const float* __restrict__ Wih0,
              const float* __restrict__ Whh0,
              const float* __restrict__ b0,
              const float* __restrict__ Wih1,
              const float* __restrict__ Whh1,
              const float* __restrict__ b1,
              const float* __restrict__ W_fc,
              const float* __restrict__ b_fc,
              float* __restrict__ out)
{
    extern __shared__ float sm[];
    float* sX   = sm + OFF_X;
    float* sY0B = sm + OFF_Y0B;
    float* sXin = sm + OFF_XIN;
    float* sH   = sm + OFF_H;
    float* sXN  = sm + OFF_XN;
    float* sGX  = sm + OFF_GX;
    float* sGH  = sm + OFF_GH;
    float* sU   = sm + OFF_U;

    const int tid  = threadIdx.x;
    const int cta  = blockIdx.x;
    const int bg   = cta * BT;
    const int lane = tid & 31;
    const int dirg = tid >> 7;             // direction
    const int q    = (tid >> 5) & 3;       // warp within dir
    const int jh   = q * 8 + (lane >> 2);  // hidden unit this lane serves
    const int cls  = lane & 3;             // gate: 0=i,1=f,2=g,3=o
    const int row  = cls * 32 + jh;        // weight row within dir
    const bool isLead = (cls == 0);
    const int loc  = tid & 127;            // staging index within dir
    // nonlinearity constants: sig(x)=0.5+0.5*tanh(0.5x); g-gate = tanh(x)
    const float nsc  = (cls == 2) ? 1.0f : 0.5f;
    const float noff = (cls == 2) ? 0.0f : 0.5f;

    // ---- per-thread weight rows in registers ----
    float w0x[DD], w0h[HH], w1f[HH], w1b[HH], w1h[HH], bias0, bias1;
    {
        const int gr = dirg * 128 + row;
#pragma unroll
        for (int k = 0; k < DD; ++k) w0x[k] = Wih0[gr * DD + k];
#pragma unroll
        for (int k = 0; k < HH; ++k) w0h[k] = Whh0[gr * HH + k];
        bias0 = b0[gr];
#pragma unroll
        for (int k = 0; k < HH; ++k) w1f[k] = Wih1[gr * 64 + k];
#pragma unroll
        for (int k = 0; k < HH; ++k) w1b[k] = Wih1[gr * 64 + 32 + k];
#pragma unroll
        for (int k = 0; k < HH; ++k) w1h[k] = Whh1[gr * HH + k];
        bias1 = b1[gr];
    }

    // ---- c-state in leader registers (lane cls==0 owns (dirg, jh, 4 batches)) ----
    float cL0[BT], cL1[BT];
#pragma unroll
    for (int b = 0; b < BT; ++b) {
        cL0[b] = c0[((size_t)dirg * NB + bg + b) * HH + jh];
        cL1[b] = c0[((size_t)(2 + dirg) * NB + bg + b) * HH + jh];
    }

    // ---- initial h (buffer 0), xn ----
    for (int e = tid; e < 4 * HH * BT; e += TPB) {
        int ld = e >> 7, k = (e >> 2) & 31, b = e & 3;
        sH[ld * 128 + k * 4 + b] = h0[((size_t)ld * NB + bg + b) * HH + k];
    }
    for (int e = tid; e < NC * BT; e += TPB) {
        int c = e >> 2, b = e & 3;
        sXN[c * BT + b] = rain_hist[((size_t)(bg + b) * NHIST + (NHIST - 1)) * NC + c];
    }
    __syncthreads();

    float* gy0cta = g_y0 + (size_t)cta * NC * 128;
    float* gy1cta = g_y1 + (size_t)cta * NC * 128;

    for (int t = 0; t < NPRED; ++t) {
        // ============ Phase 1: build x tile (slot0=g, slot1=xn, 2..14=feat) ============
        for (int e = tid; e < NC * NFEAT * BT; e += TPB) {
            int b = e / (NC * NFEAT);
            int rem = e - b * (NC * NFEAT);
            int c = rem / NFEAT;
            int kk = rem - c * NFEAT;
            sX[(c * 16 + 2 + kk) * BT + b] =
                feature[(((size_t)(bg + b) * FTOT + NHIST + t) * NC + c) * NFEAT + kk];
        }
        for (int e = tid; e < NC * BT; e += TPB) {
            int c = e >> 2, b = e & 3;
            sX[(c * 16 + 1) * BT + b] = sXN[c * BT + b];
        }
        __syncthreads();

        // ============ Phase 2: gated graph MLP (4-way c-split chains) ============
        if (tid < NC) {
            const int j = tid;
            u64 A0 = pk2(b_mlp[j]), A1 = 0, A2 = 0, A3 = 0;
            u64 B0 = A0, B1 = 0, B2 = 0, B3 = 0;
            for (int c = 0; c < NC; c += 4) {
#pragma unroll
                for (int p = 0; p < 4; ++p) {
                    const float* wp = W_mlp + ((size_t)(c + p) * IND) * NC + j;
                    const ulonglong2* xp = (const ulonglong2*)(sX + ((c + p) * 16 + 1) * BT);
#pragma unroll
                    for (int kk = 0; kk < IND; ++kk) {
                        u64 w = pk2(wp[(size_t)kk * NC]);
                        ulonglong2 xv = xp[kk];
                        if (p == 0) { ffma2(A0, xv.x, w); ffma2(B0, xv.y, w); }
                        if (p == 1) { ffma2(A1, xv.x, w); ffma2(B1, xv.y, w); }
                        if (p == 2) { ffma2(A2, xv.x, w); ffma2(B2, xv.y, w); }
                        if (p == 3) { ffma2(A3, xv.x, w); ffma2(B3, xv.y, w); }
                    }
                }
            }
            float2 v01 = unpk(addx2(addx2(A0, A1), addx2(A2, A3)));
            float2 v23 = unpk(addx2(addx2(B0, B1), addx2(B2, B3)));
            sX[(j * 16) * BT + 0] = sigf(v01.x);
            sX[(j * 16) * BT + 1] = sigf(v01.y);
            sX[(j * 16) * BT + 2] = sigf(v23.x);
            sX[(j * 16) * BT + 3] = sigf(v23.y);
        }
        __syncthreads();

        // ============ Phase 3: GRU cell (h buffer 0) ============
        for (int e = tid; e < BT * DD; e += TPB) {
            int b = e / DD, k = e - b * DD;
            float s = 0.0f;
            for (int c = 0; c < NC; ++c) s += sX[(c * 16 + k) * BT + b];
            sU[b * 16 + k] = s * (1.0f / NC);
        }
        __syncthreads();
        for (int e = tid; e < BT * 96; e += TPB) {
            int b = e / 96, j = e - b * 96;
            float a = b_ih_g[j];
#pragma unroll
            for (int k = 0; k < DD; ++k)
                a = fmaf(sU[b * 16 + k], Wih_g[k * 96 + j], a);
            sGX[e] = a;
        }
        for (int e = tid; e < 16 * 96; e += TPB) {
            int lb = e / 96, j = e - lb * 96;
            int l = lb >> 2, b = lb & 3;
            float a = b_hh_g[j];
#pragma unroll
            for (int k = 0; k < HH; ++k)
                a = fmaf(sH[l * 128 + k * 4 + b], Whh_g[k * 96 + j], a);
            sGH[e] = a;
        }
        __syncthreads();
        for (int e = tid; e < 4 * BT * HH; e += TPB) {
            int l = e >> 7, b = (e >> 5) & 3, j = e & 31;
            int gb = b * 96, ghb = (l * BT + b) * 96;
            float r = sigf(sGX[gb + j]      + sGH[ghb + j]);
            float z = sigf(sGX[gb + 32 + j] + sGH[ghb + 32 + j]);
            float n = tanhfast(sGX[gb + 64 + j] + r * sGH[ghb + 64 + j]);
            int hi = l * 128 + j * 4 + b;
            sH[hi] = (1.0f - z) * n + z * sH[hi];
        }
        __syncthreads();

        // ============ Phase 4: BiLSTM layer 0 — single barrier per city step ============
        {
            int buf = 0;
            u64 a01, a23;
            {   // x-part prologue for s = 0
                int city = dirg ? (NC - 1) : 0;
                const ulonglong2* xp = (const ulonglong2*)(sX + city * 64);
                a01 = pk2(bias0); a23 = a01;
#pragma unroll
                for (int k = 0; k < DD; ++k) {
                    u64 w = pk2(w0x[k]);
                    ulonglong2 xv = xp[k];
                    ffma2(a01, xv.x, w); ffma2(a23, xv.y, w);
                }
            }
            for (int s = 0; s < NC; ++s) {
                // h-part on current buffer
                const ulonglong2* hp = (const ulonglong2*)(sH + buf * 512 + dirg * 128);
#pragma unroll
                for (int k = 0; k < HH; ++k) {
                    u64 w = pk2(w0h[k]);
                    ulonglong2 hv = hp[k];
                    ffma2(a01, hv.x, w); ffma2(a23, hv.y, w);
                }
                float2 v01 = unpk(a01), v23 = unpk(a23);
                float g0 = noff + nsc * tanhfast(nsc * v01.x);
                float g1 = noff + nsc * tanhfast(nsc * v01.y);
                float g2 = noff + nsc * tanhfast(nsc * v23.x);
                float g3 = noff + nsc * tanhfast(nsc * v23.y);
                // gather f,g,o into the i-lane (leader)
                float f0 = __shfl_sync(0xffffffffu, g0, lane + 1);
                float f1 = __shfl_sync(0xffffffffu, g1, lane + 1);
                float f2 = __shfl_sync(0xffffffffu, g2, lane + 1);
                float f3 = __shfl_sync(0xffffffffu, g3, lane + 1);
                float c0_ = __shfl_sync(0xffffffffu, g0, lane + 2);
                float c1_ = __shfl_sync(0xffffffffu, g1, lane + 2);
                float c2_ = __shfl_sync(0xffffffffu, g2, lane + 2);
                float c3_ = __shfl_sync(0xffffffffu, g3, lane + 2);
                float o0 = __shfl_sync(0xffffffffu, g0, lane + 3);
                float o1 = __shfl_sync(0xffffffffu, g1, lane + 3);
                float o2 = __shfl_sync(0xffffffffu, g2, lane + 3);
                float o3 = __shfl_sync(0xffffffffu, g3, lane + 3);
                if (isLead) {
                    cL0[0] = fmaf(f0, cL0[0], g0 * c0_);
                    cL0[1] = fmaf(f1, cL0[1], g1 * c1_);
                    cL0[2] = fmaf(f2, cL0[2], g2 * c2_);
                    cL0[3] = fmaf(f3, cL0[3], g3 * c3_);
                    float4 hv4 = make_float4(o0 * tanhfast(cL0[0]),
                                             o1 * tanhfast(cL0[1]),
                                             o2 * tanhfast(cL0[2]),
                                             o3 * tanhfast(cL0[3]));
                    int city = dirg ? (NC - 1 - s) : s;
                    *(float4*)(sH + (buf ^ 1) * 512 + dirg * 128 + jh * 4) = hv4;
                    if (dirg == 0)
                        *(float4*)(gy0cta + city * 128 + jh * 4) = hv4;
                    else
                        *(float4*)(sY0B + city * 128 + jh * 4) = hv4;
                }
                // window: x-part(s+1)
                if (s + 1 < NC) {
                    int cityn = dirg ? (NC - 2 - s) : (s + 1);
                    const ulonglong2* xp = (const ulonglong2*)(sX + cityn * 64);
                    a01 = pk2(bias0); a23 = a01;
#pragma unroll
                    for (int k = 0; k < DD; ++k) {
                        u64 w = pk2(w0x[k]);
                        ulonglong2 xv = xp[k];
                        ffma2(a01, xv.x, w); ffma2(a23, xv.y, w);
                    }
                }
                __syncthreads();
                buf ^= 1;
            }
        }

        // ============ Phase 5: BiLSTM layer 1 — single barrier per city step ============
        {
            int buf = 0;
            float pf;
            // prologue: stage y0f(0) and y0f(1), prefetch y0f(2)
            {
                int c0i = dirg ? (NC - 1) : 0;
                int c1i = dirg ? (NC - 2) : 1;
                int c2i = dirg ? (NC - 3) : 2;
                sXin[dirg * 256 + 0   + loc] = gy0cta[c0i * 128 + loc];
                sXin[dirg * 256 + 128 + loc] = gy0cta[c1i * 128 + loc];
                pf = gy0cta[c2i * 128 + loc];
            }
            __syncthreads();
            u64 a01, a23;
            {   // fb-part for s = 0
                const ulonglong2* fp = (const ulonglong2*)(sXin + dirg * 256);
                int city = dirg ? (NC - 1) : 0;
                const ulonglong2* bp = (const ulonglong2*)(sY0B + city * 128);
                a01 = pk2(bias1); a23 = a01;
#pragma unroll
                for (int k = 0; k < HH; ++k) {
                    u64 w = pk2(w1f[k]);
                    ulonglong2 yv = fp[k];
                    ffma2(a01, yv.x, w); ffma2(a23, yv.y, w);
                }
#pragma unroll
                for (int k = 0; k < HH; ++k) {
                    u64 w = pk2(w1b[k]);
                    ulonglong2 bv = bp[k];
                    ffma2(a01, bv.x, w); ffma2(a23, bv.y, w);
                }
            }
            for (int s = 0; s < NC; ++s) {
                // h-part
                const ulonglong2* hp = (const ulonglong2*)(sH + buf * 512 + (2 + dirg) * 128);
#pragma unroll
                for (int k = 0; k < HH; ++k) {
                    u64 w = pk2(w1h[k]);
                    ulonglong2 hv = hp[k];
                    ffma2(a01, hv.x, w); ffma2(a23, hv.y, w);
                }
                float2 v01 = unpk(a01), v23 = unpk(a23);
                float g0 = noff + nsc * tanhfast(nsc * v01.x);
                float g1 = noff + nsc * tanhfast(nsc * v01.y);
                float g2 = noff + nsc * tanhfast(nsc * v23.x);
                float g3 = noff + nsc * tanhfast(nsc * v23.y);
                float f0 = __shfl_sync(0xffffffffu, g0, lane + 1);
                float f1 = __shfl_sync(0xffffffffu, g1, lane + 1);
                float f2 = __shfl_sync(0xffffffffu, g2, lane + 1);
                float f3 = __shfl_sync(0xffffffffu, g3, lane + 1);
                float c0_ = __shfl_sync(0xffffffffu, g0, lane + 2);
                float c1_ = __shfl_sync(0xffffffffu, g1, lane + 2);
                float c2_ = __shfl_sync(0xffffffffu, g2, lane + 2);
                float c3_ = __shfl_sync(0xffffffffu, g3, lane + 2);
                float o0 = __shfl_sync(0xffffffffu, g0, lane + 3);
                float o1 = __shfl_sync(0xffffffffu, g1, lane + 3);
                float o2 = __shfl_sync(0xffffffffu, g2, lane + 3);
                float o3 = __shfl_sync(0xffffffffu, g3, lane + 3);
                if (isLead) {
                    cL1[0] = fmaf(f0, cL1[0], g0 * c0_);
                    cL1[1] = fmaf(f1, cL1[1], g1 * c1_);
                    cL1[2] = fmaf(f2, cL1[2], g2 * c2_);
                    cL1[3] = fmaf(f3, cL1[3], g3 * c3_);
                    float4 hv4 = make_float4(o0 * tanhfast(cL1[0]),
                                             o1 * tanhfast(cL1[1]),
                                             o2 * tanhfast(cL1[2]),
                                             o3 * tanhfast(cL1[3]));
                    *(float4*)(sH + (buf ^ 1) * 512 + (2 + dirg) * 128 + jh * 4) = hv4;
                    if (dirg == 0)
                        *(float4*)(gy1cta + s * 128 + jh * 4) = hv4;
                }
                // window: stash y0f(s+2), prefetch y0f(s+3), fb-part(s+1)
                if (s + 2 < NC)
                    sXin[dirg * 256 + (s & 1) * 128 + loc] = pf;
                {
                    int cp = s + 3; if (cp > NC - 1) cp = NC - 1;
                    int cc = dirg ? (NC - 1 - cp) : cp;
                    pf = gy0cta[cc * 128 + loc];
                }
                if (s + 1 < NC) {
                    const ulonglong2* fp =
                        (const ulonglong2*)(sXin + dirg * 256 + ((s + 1) & 1) * 128);
                    int cityn = dirg ? (NC - 2 - s) : (s + 1);
                    const ulonglong2* bp = (const ulonglong2*)(sY0B + cityn * 128);
                    a01 = pk2(bias1); a23 = a01;
#pragma unroll
                    for (int k = 0; k < HH; ++k) {
                        u64 w = pk2(w1f[k]);
                        ulonglong2 yv = fp[k];
                        ffma2(a01, yv.x, w); ffma2(a23, yv.y, w);
                    }
#pragma unroll
                    for (int k = 0; k < HH; ++k) {
                        u64 w = pk2(w1b[k]);
                        ulonglong2 bv = bp[k];
                        ffma2(a01, bv.x, w); ffma2(a23, bv.y, w);
                    }
                }
                __syncthreads();
                buf ^= 1;
            }
        }

        // ============ Phase 6: FC head (parallel epilogue) ============
        {
            const float bfc = b_fc[0];
            for (int e = tid; e < NC * BT; e += TPB) {
                int c = e >> 2, b = e & 3;
                const float* yp = gy1cta + c * 128 + b;
                float a = bfc;
#pragma unroll
                for (int j = 0; j < HH; ++j)
                    a = fmaf(yp[j * 4], W_fc[j], a);
                sXN[c * BT + b] = a;
                out[((size_t)(bg + b) * NPRED + t) * NC + c] = a;
            }
        }
        __syncthreads();
    }
}

extern "C" void kernel_launch(void* const* d_in, const int* in_sizes, int n_in,
                              void* d_out, int out_size) {
    (void)in_sizes; (void)n_in; (void)out_size;
    const float* rain_hist = (const float*)d_in[0];
    const float* feature   = (const float*)d_in[1];
    const float* h0        = (const float*)d_in[2];
    const float* c0        = (const float*)d_in[3];
    const float* W_mlp     = (const float*)d_in[4];
    const float* b_mlp     = (const float*)d_in[5];
    const float* Wih_g     = (const float*)d_in[6];
    const float* Whh_g     = (const float*)d_in[7];
    const float* b_ih_g    = (const float*)d_in[8];
    const float* b_hh_g    = (const float*)d_in[9];
    const float* Wih0      = (const float*)d_in[10];
    const float* Whh0      = (const float*)d_in[11];
    const float* b0        = (const float*)d_in[12];
    const float* Wih1      = (const float*)d_in[13];
    const float* Whh1      = (const float*)d_in[14];
    const float* b1        = (const float*)d_in[15];
    const float* W_fc      = (const float*)d_in[16];
    const float* b_fc      = (const float*)d_in[17];

    size_t smem = (size_t)SMEM_FLOATS * sizeof(float);
    cudaFuncSetAttribute(bilstm_kernel,
                         cudaFuncAttributeMaxDynamicSharedMemorySize, (int)smem);
    bilstm_kernel<<<NCTA, TPB, smem>>>(
        rain_hist, feature, h0, c0, W_mlp, b_mlp,
        Wih_g, Whh_g, b_ih_g, b_hh_g,
        Wih0, Whh0, b0, Wih1, Whh1, b1,
        W_fc, b_fc, (float*)d_out);
}

// round 9
// speedup vs baseline: 1.6277x; 1.0095x over previous
#include <cuda_runtime.h>

// Problem constants
#define NCTA   128
#define TPB    256
#define NB     512
#define BT     4
#define NC     184
#define HH     32
#define IND    14
#define DD     15
#define NPRED  24
#define NHIST  24
#define NFEAT  13
#define FTOT   48

// Global scratch (per-CTA private slices; same-CTA produce/consume)
__device__ float g_y0[(size_t)NCTA * NC * BT * HH];   // fwd y0

// Shared memory layout (float offsets)
#define OFF_X    0        // 184*16*4 = 11776  x tile [c][k16][b]
#define OFF_Y0B  11776    // 184*32*4 = 23552  bwd y0 [c][j][b]
#define OFF_XIN  35328    // 2dir*2buf*128     staged fwd y0 [k][b]
#define OFF_G    35840    // 2*4*128  = 1024   raw gates [dir][b][row]
#define OFF_H    36864    // 4*32*4   = 512    h state [ld][j][b]
#define OFF_C    37376    // 4*32*4   = 512    c state [ld][j][b]
#define OFF_XN   37888    // 184*4    = 736
#define OFF_GX   38624    // 384
#define OFF_GH   39008    // 1536
#define OFF_U    40544    // 64
#define SMEM_FLOATS 40608 // 162,432 bytes

typedef unsigned long long u64;

__device__ __forceinline__ u64 pk2(float w) {
    u64 r; asm("mov.b64 %0, {%1, %1};" : "=l"(r) : "f"(w)); return r;
}
__device__ __forceinline__ void ffma2(u64& a, u64 x, u64 w) {
    asm("fma.rn.f32x2 %0, %1, %2, %0;" : "+l"(a) : "l"(x), "l"(w));
}
__device__ __forceinline__ u64 addx2(u64 a, u64 b) {
    u64 r; asm("add.rn.f32x2 %0, %1, %2;" : "=l"(r) : "l"(a), "l"(b)); return r;
}
__device__ __forceinline__ float2 unpk(u64 a) {
    float2 f; asm("mov.b64 {%0, %1}, %2;" : "=f"(f.x), "=f"(f.y) : "l"(a)); return f;
}
__device__ __forceinline__ float sigf(float x) {
    return __fdividef(1.0f, 1.0f + __expf(-x));
}
__device__ __forceinline__ float tanhfast(float x) {
    x = fminf(fmaxf(x, -15.0f), 15.0f);
    float e = __expf(2.0f * x);
    return __fdividef(e - 1.0f, e + 1.0f);
}

__global__ void __launch_bounds__(TPB, 1)
bilstm_kernel(const float* __restrict__ rain_hist,
              const float* __restrict__ feature,
              const float* __restrict__ h0,
              const float* __restrict__ c0,
              const float* __restrict__ W_mlp,
              const float* __restrict__ b_mlp,
              const float* __restrict__ Wih_g,
              const float* __restrict__ Whh_g,
              const float* __restrict__ b_ih_g,
              const float* __restrict__ b_hh_g,
              const float* __restrict__ Wih0,
              const float* __restrict__ Whh0,
              const float* __restrict__ b0,
              const float* __restrict__ Wih1,
              const float* __restrict__ Whh1,
              const float* __restrict__ b1,
              const float* __restrict__ W_fc,
              const float* __restrict__ b_fc,
              float* __restrict__ out)
{
    extern __shared__ float sm[];
    float* sX   = sm + OFF_X;
    float* sY0B = sm + OFF_Y0B;
    float* sXin = sm + OFF_XIN;
    float* sG   = sm + OFF_G;
    float* sH   = sm + OFF_H;
    float* sCst = sm + OFF_C;
    float* sXN  = sm + OFF_XN;
    float* sGX  = sm + OFF_GX;
    float* sGH  = sm + OFF_GH;
    float* sU   = sm + OFF_U;

    const int tid  = threadIdx.x;
    const int cta  = blockIdx.x;
    const int bg   = cta * BT;
    const int dirg = tid >> 7;          // gate-phase direction / update du
    const int jg   = tid & 127;         // gate row within dir
    const int bu   = (tid >> 5) & 3;    // update-phase batch
    const int ju   = tid & 31;          // update-phase hidden idx
    const int row  = dirg * 128 + jg;
    const int loc  = tid & 127;
    const int kst  = loc & 31, bst = loc >> 5;   // staging (k,b)

    const float wfc = W_fc[ju];
    const float bfc = b_fc[0];

    // ---- initial states ----
    for (int e = tid; e < 4 * HH * BT; e += TPB) {
        int ld = e >> 7, k = (e >> 2) & 31, b = e & 3;
        sH[(ld * HH + k) * BT + b]   = h0[((size_t)ld * NB + bg + b) * HH + k];
        sCst[(ld * HH + k) * BT + b] = c0[((size_t)ld * NB + bg + b) * HH + k];
    }
    for (int e = tid; e < NC * BT; e += TPB) {
        int c = e >> 2, b = e & 3;
        sXN[c * BT + b] = rain_hist[((size_t)(bg + b) * NHIST + (NHIST - 1)) * NC + c];
    }
    __syncthreads();

    for (int t = 0; t < NPRED; ++t) {
        // opaque zero (loop-variant to the compiler) -> keeps weight loads inside
        // the t-loop so packed-weight live ranges stay phase-scoped (no spills)
        int zr; asm volatile("mov.u32 %0, %1;" : "=r"(zr) : "r"(0));
        const int rowz = row + zr;

        // ============ Phase 1: build x tile (slot0=g, slot1=xn, 2..14=feat) ============
        for (int e = tid; e < NC * NFEAT * BT; e += TPB) {
            int b = e / (NC * NFEAT);
            int rem = e - b * (NC * NFEAT);
            int c = rem / NFEAT;
            int kk = rem - c * NFEAT;
            sX[(c * 16 + 2 + kk) * BT + b] =
                feature[(((size_t)(bg + b) * FTOT + NHIST + t) * NC + c) * NFEAT + kk];
        }
        for (int e = tid; e < NC * BT; e += TPB) {
            int c = e >> 2, b = e & 3;
            sX[(c * 16 + 1) * BT + b] = sXN[c * BT + b];
        }
        __syncthreads();

        // ============ Phase 2: gated graph MLP (in-loop, 4-way c-split chains) ============
        if (tid < NC) {
            const int j = tid;
            u64 A0 = pk2(b_mlp[j]), A1 = 0, A2 = 0, A3 = 0;
            u64 B0 = A0, B1 = 0, B2 = 0, B3 = 0;
            for (int c = 0; c < NC; c += 4) {
#pragma unroll
                for (int p = 0; p < 4; ++p) {
                    const float* wp = W_mlp + ((size_t)(c + p) * IND) * NC + j;
                    const ulonglong2* xp = (const ulonglong2*)(sX + ((c + p) * 16 + 1) * BT);
#pragma unroll
                    for (int kk = 0; kk < IND; ++kk) {
                        u64 w = pk2(wp[(size_t)kk * NC]);
                        ulonglong2 xv = xp[kk];
                        if (p == 0) { ffma2(A0, xv.x, w); ffma2(B0, xv.y, w); }
                        if (p == 1) { ffma2(A1, xv.x, w); ffma2(B1, xv.y, w); }
                        if (p == 2) { ffma2(A2, xv.x, w); ffma2(B2, xv.y, w); }
                        if (p == 3) { ffma2(A3, xv.x, w); ffma2(B3, xv.y, w); }
                    }
                }
            }
            float2 v01 = unpk(addx2(addx2(A0, A1), addx2(A2, A3)));
            float2 v23 = unpk(addx2(addx2(B0, B1), addx2(B2, B3)));
            sX[(j * 16) * BT + 0] = sigf(v01.x);
            sX[(j * 16) * BT + 1] = sigf(v01.y);
            sX[(j * 16) * BT + 2] = sigf(v23.x);
            sX[(j * 16) * BT + 3] = sigf(v23.y);
        }
        __syncthreads();

        // ============ Phase 3: GRU cell ============
        for (int e = tid; e < BT * DD; e += TPB) {
            int b = e / DD, k = e - b * DD;
            float s = 0.0f;
            for (int c = 0; c < NC; ++c) s += sX[(c * 16 + k) * BT + b];
            sU[b * 16 + k] = s * (1.0f / NC);
        }
        __syncthreads();
        for (int e = tid; e < BT * 96; e += TPB) {
            int b = e / 96, j = e - b * 96;
            float a = b_ih_g[j];
#pragma unroll
            for (int k = 0; k < DD; ++k)
                a = fmaf(sU[b * 16 + k], Wih_g[k * 96 + j], a);
            sGX[e] = a;
        }
        for (int e = tid; e < 16 * 96; e += TPB) {
            int lb = e / 96, j = e - lb * 96;
            int l = lb >> 2, b = lb & 3;
            float a = b_hh_g[j];
#pragma unroll
            for (int k = 0; k < HH; ++k)
                a = fmaf(sH[(l * HH + k) * BT + b], Whh_g[k * 96 + j], a);
            sGH[e] = a;
        }
        __syncthreads();
        for (int e = tid; e < 4 * BT * HH; e += TPB) {
            int l = e >> 7, b = (e >> 5) & 3, j = e & 31;
            int gb = b * 96, ghb = (l * BT + b) * 96;
            float r = sigf(sGX[gb + j]      + sGH[ghb + j]);
            float z = sigf(sGX[gb + 32 + j] + sGH[ghb + 32 + j]);
            float n = tanhfast(sGX[gb + 64 + j] + r * sGH[ghb + 64 + j]);
            int hi = (l * HH + j) * BT + b;
            sH[hi] = (1.0f - z) * n + z * sH[hi];
        }
        __syncthreads();

        // ============ Phase 4: BiLSTM layer 0 (pre-packed weights, phase-scoped) ====
        {
            u64 W0X[DD], W0H[HH], B0P;
#pragma unroll
            for (int k = 0; k < DD; ++k) W0X[k] = pk2(Wih0[rowz * DD + k]);
#pragma unroll
            for (int k = 0; k < HH; ++k) W0H[k] = pk2(Whh0[rowz * HH + k]);
            B0P = pk2(b0[rowz]);

            u64 x01, x23;
            {   // x-part prologue s = 0
                int city = dirg ? (NC - 1) : 0;
                const ulonglong2* xp = (const ulonglong2*)(sX + city * 64);
                x01 = B0P; x23 = B0P;
#pragma unroll
                for (int k = 0; k < DD; ++k) {
                    ulonglong2 xv = xp[k];
                    ffma2(x01, xv.x, W0X[k]); ffma2(x23, xv.y, W0X[k]);
                }
            }
            for (int s = 0; s < NC; ++s) {
                // h-part: 2 chains of 16 per output pair
                const ulonglong2* hp = (const ulonglong2*)(sH + dirg * HH * BT);
                u64 hA01 = 0, hA23 = 0, hB01 = 0, hB23 = 0;
#pragma unroll
                for (int k = 0; k < 16; ++k) {
                    ulonglong2 hv = hp[k];
                    ffma2(hA01, hv.x, W0H[k]); ffma2(hA23, hv.y, W0H[k]);
                }
#pragma unroll
                for (int k = 0; k < 16; ++k) {
                    ulonglong2 hv = hp[16 + k];
                    ffma2(hB01, hv.x, W0H[16 + k]); ffma2(hB23, hv.y, W0H[16 + k]);
                }
                float2 v01 = unpk(addx2(x01, addx2(hA01, hB01)));
                float2 v23 = unpk(addx2(x23, addx2(hA23, hB23)));
                float* gp = sG + dirg * 512 + jg;
                gp[0] = v01.x; gp[128] = v01.y; gp[256] = v23.x; gp[384] = v23.y;
                __syncthreads();
                // window: update(s) + x-part(s+1)
                {
                    const float* g = sG + dirg * 512 + bu * 128;
                    float iv = sigf(g[ju]);
                    float fv = sigf(g[32 + ju]);
                    float gv = tanhfast(g[64 + ju]);
                    float ov = sigf(g[96 + ju]);
                    int ci = (dirg * HH + ju) * BT + bu;
                    float cc = fmaf(fv, sCst[ci], iv * gv);
                    sCst[ci] = cc;
                    float h = ov * tanhfast(cc);
                    sH[ci] = h;
                    int cityu = dirg ? (NC - 1 - s) : s;
                    if (dirg == 0)
                        g_y0[((size_t)(cta * NC + cityu) * BT + bu) * HH + ju] = h;
                    else
                        sY0B[cityu * 128 + ju * 4 + bu] = h;
                }
                if (s + 1 < NC) {
                    int cityn = dirg ? (NC - 2 - s) : (s + 1);
                    const ulonglong2* xp = (const ulonglong2*)(sX + cityn * 64);
                    x01 = B0P; x23 = B0P;
#pragma unroll
                    for (int k = 0; k < DD; ++k) {
                        ulonglong2 xv = xp[k];
                        ffma2(x01, xv.x, W0X[k]); ffma2(x23, xv.y, W0X[k]);
                    }
                }
                __syncthreads();
            }
        }

        // ============ Phase 5: BiLSTM layer 1 (pre-packed weights, phase-scoped) ====
        {
            u64 W1F[HH], W1B[HH], W1H[HH], B1P;
#pragma unroll
            for (int k = 0; k < HH; ++k) W1F[k] = pk2(Wih1[rowz * 64 + k]);
#pragma unroll
            for (int k = 0; k < HH; ++k) W1B[k] = pk2(Wih1[rowz * 64 + 32 + k]);
#pragma unroll
            for (int k = 0; k < HH; ++k) W1H[k] = pk2(Whh1[rowz * HH + k]);
            B1P = pk2(b1[rowz]);

            u64 fb01, fb23;
            float pf;
            {   // prologue: stage y0f(0), prefetch y0f(1), y0b-part(0)
                int c0_ = dirg ? (NC - 1) : 0;
                sXin[(dirg * 2 + 0) * 128 + kst * 4 + bst] =
                    g_y0[((size_t)(cta * NC + c0_) * BT + bst) * HH + kst];
                int c1_ = dirg ? (NC - 2) : 1;
                pf = g_y0[((size_t)(cta * NC + c1_) * BT + bst) * HH + kst];
                int city = dirg ? (NC - 1) : 0;
                const ulonglong2* bp2 = (const ulonglong2*)(sY0B + city * 128);
                u64 bA01 = B1P, bA23 = B1P, bB01 = 0, bB23 = 0;
#pragma unroll
                for (int k = 0; k < 16; ++k) {
                    ulonglong2 bv = bp2[k];
                    ffma2(bA01, bv.x, W1B[k]); ffma2(bA23, bv.y, W1B[k]);
                }
#pragma unroll
                for (int k = 0; k < 16; ++k) {
                    ulonglong2 bv = bp2[16 + k];
                    ffma2(bB01, bv.x, W1B[16 + k]); ffma2(bB23, bv.y, W1B[16 + k]);
                }
                fb01 = addx2(bA01, bB01); fb23 = addx2(bA23, bB23);
            }
            __syncthreads();
            int buf = 0;
            for (int s = 0; s < NC; ++s) {
                // f-part (staged y0f) + h-part: 4 chains of 16
                const ulonglong2* fp2 = (const ulonglong2*)(sXin + (dirg * 2 + buf) * 128);
                const ulonglong2* hp  = (const ulonglong2*)(sH + (2 + dirg) * HH * BT);
                u64 fA01 = 0, fA23 = 0, fB01 = 0, fB23 = 0;
                u64 hA01 = 0, hA23 = 0, hB01 = 0, hB23 = 0;
#pragma unroll
                for (int k = 0; k < 16; ++k) {
                    ulonglong2 yv = fp2[k];
                    ffma2(fA01, yv.x, W1F[k]); ffma2(fA23, yv.y, W1F[k]);
                }
#pragma unroll
                for (int k = 0; k < 16; ++k) {
                    ulonglong2 yv = fp2[16 + k];
                    ffma2(fB01, yv.x, W1F[16 + k]); ffma2(fB23, yv.y, W1F[16 + k]);
                }
#pragma unroll
                for (int k = 0; k < 16; ++k) {
                    ulonglong2 hv = hp[k];
                    ffma2(hA01, hv.x, W1H[k]); ffma2(hA23, hv.y, W1H[k]);
                }
#pragma unroll
                for (int k = 0; k < 16; ++k) {
                    ulonglong2 hv = hp[16 + k];
                    ffma2(hB01, hv.x, W1H[16 + k]); ffma2(hB23, hv.y, W1H[16 + k]);
                }
                float2 v01 = unpk(addx2(addx2(fb01, addx2(fA01, fB01)), addx2(hA01, hB01)));
                float2 v23 = unpk(addx2(addx2(fb23, addx2(fA23, fB23)), addx2(hA23, hB23)));
                float* gp = sG + dirg * 512 + jg;
                gp[0] = v01.x; gp[128] = v01.y; gp[256] = v23.x; gp[384] = v23.y;
                __syncthreads();
                // window: stash y0f(s+1), prefetch y0f(s+2), update(s), y0b-part(s+1)
                if (s + 1 < NC)
                    sXin[(dirg * 2 + (buf ^ 1)) * 128 + kst * 4 + bst] = pf;
                if (s + 2 < NC) {
                    int cp = dirg ? (NC - 3 - s) : (s + 2);
                    pf = g_y0[((size_t)(cta * NC + cp) * BT + bst) * HH + kst];
                }
                {
                    const float* g = sG + dirg * 512 + bu * 128;
                    float iv = sigf(g[ju]);
                    float fv = sigf(g[32 + ju]);
                    float gv = tanhfast(g[64 + ju]);
                    float ov = sigf(g[96 + ju]);
                    int ci = ((2 + dirg) * HH + ju) * BT + bu;
                    float cc = fmaf(fv, sCst[ci], iv * gv);
                    sCst[ci] = cc;
                    float h = ov * tanhfast(cc);
                    sH[ci] = h;
                    if (dirg == 0) {
                        // inline FC head (fwd half only)
                        float v = wfc * h;
                        v += __shfl_xor_sync(0xffffffffu, v, 16);
                        v += __shfl_xor_sync(0xffffffffu, v, 8);
                        v += __shfl_xor_sync(0xffffffffu, v, 4);
                        v += __shfl_xor_sync(0xffffffffu, v, 2);
                        v += __shfl_xor_sync(0xffffffffu, v, 1);
                        if (ju == 0) {
                            float a = v + bfc;
                            sXN[s * BT + bu] = a;
                            out[((size_t)(bg + bu) * NPRED + t) * NC + s] = a;
                        }
                    }
                }
                if (s + 1 < NC) {
                    int cityn = dirg ? (NC - 2 - s) : (s + 1);
                    const ulonglong2* bp2 = (const ulonglong2*)(sY0B + cityn * 128);
                    u64 bA01 = B1P, bA23 = B1P, bB01 = 0, bB23 = 0;
#pragma unroll
                    for (int k = 0; k < 16; ++k) {
                        ulonglong2 bv = bp2[k];
                        ffma2(bA01, bv.x, W1B[k]); ffma2(bA23, bv.y, W1B[k]);
                    }
#pragma unroll
                    for (int k = 0; k < 16; ++k) {
                        ulonglong2 bv = bp2[16 + k];
                        ffma2(bB01, bv.x, W1B[16 + k]); ffma2(bB23, bv.y, W1B[16 + k]);
                    }
                    fb01 = addx2(bA01, bB01); fb23 = addx2(bA23, bB23);
                }
                __syncthreads();
                buf ^= 1;
            }
        }
        __syncthreads();
    }
}

extern "C" void kernel_launch(void* const* d_in, const int* in_sizes, int n_in,
                              void* d_out, int out_size) {
    (void)in_sizes; (void)n_in; (void)out_size;
    const float* rain_hist = (const float*)d_in[0];
    const float* feature   = (const float*)d_in[1];
    const float* h0        = (const float*)d_in[2];
    const float* c0        = (const float*)d_in[3];
    const float* W_mlp     = (const float*)d_in[4];
    const float* b_mlp     = (const float*)d_in[5];
    const float* Wih_g     = (const float*)d_in[6];
    const float* Whh_g     = (const float*)d_in[7];
    const float* b_ih_g    = (const float*)d_in[8];
    const float* b_hh_g    = (const float*)d_in[9];
    const float* Wih0      = (const float*)d_in[10];
    const float* Whh0      = (const float*)d_in[11];
    const float* b0        = (const float*)d_in[12];
    const float* Wih1      = (const float*)d_in[13];
    const float* Whh1      = (const float*)d_in[14];
    const float* b1        = (const float*)d_in[15];
    const float* W_fc      = (const float*)d_in[16];
    const float* b_fc      = (const float*)d_in[17];

    size_t smem = (size_t)SMEM_FLOATS * sizeof(float);
    cudaFuncSetAttribute(bilstm_kernel,
                         cudaFuncAttributeMaxDynamicSharedMemorySize, (int)smem);
    bilstm_kernel<<<NCTA, TPB, smem>>>(
        rain_hist, feature, h0, c0, W_mlp, b_mlp,
        Wih_g, Whh_g, b_ih_g, b_hh_g,
        Wih0, Whh0, b0, Wih1, Whh1, b1,
        W_fc, b_fc, (float*)d_out);
}

// round 10
// speedup vs baseline: 1.9067x; 1.1714x over previous
#include <cuda_runtime.h>

// Problem constants
#define NCTA   128
#define TPB    256
#define NB     512
#define BT     4       // batch elements per CTA
#define NC     184     // cities
#define HH     32      // hidden
#define IND    14      // in_dim
#define DD     15      // in_dim + 1
#define NPRED  24
#define NHIST  24
#define NFEAT  13      // in_dim - 1
#define FTOT   48      // hist + pred

// Global scratch (per-CTA private slices; same-CTA produce/consume only)
__device__ float g_y0[(size_t)NCTA * NC * BT * 64];

// Shared memory layout (float offsets, all 16B-aligned where vector-loaded)
#define OFF_X    0        // 184*15*4 = 11040   x tile [c][k][b]
#define OFF_XIN  11040    // 2*512    = 1024    layer1 staged input, double-buffered
#define OFF_G    12064    // 2*4*128  = 1024    gate buffer [dir][b][j]
#define OFF_H    13088    // 4*32*4   = 512     h state [ld][k][b]
#define OFF_C    13600    // 4*32*4   = 512     c state [ld][k][b]
#define OFF_XN   14112    // 184*4    = 736     xn [c][b]
#define OFF_GX   14848    // 4*96     = 384
#define OFF_GH   15232    // 16*96    = 1536
#define OFF_U    16768    // 4*16     = 64
#define OFF_Y1   16832    // 184*4*32 = 23552   y1 forward half [c][b][j]
#define SMEM_FLOATS 40384 // 161,536 bytes

typedef unsigned long long u64;

__device__ __forceinline__ u64 pk2(float w) {
    u64 r;
    asm("mov.b64 %0, {%1, %1};" : "=l"(r) : "f"(w));
    return r;
}
__device__ __forceinline__ void ffma2(u64& a, u64 x, u64 w) {
    asm("fma.rn.f32x2 %0, %1, %2, %0;" : "+l"(a) : "l"(x), "l"(w));
}
__device__ __forceinline__ u64 addx2(u64 a, u64 b) {
    u64 r;
    asm("add.rn.f32x2 %0, %1, %2;" : "=l"(r) : "l"(a), "l"(b));
    return r;
}
__device__ __forceinline__ float2 unpk(u64 a) {
    float2 f;
    asm("mov.b64 {%0, %1}, %2;" : "=f"(f.x), "=f"(f.y) : "l"(a));
    return f;
}

// hardware tanh (MUFU.TANH, sm_90+): single instruction
__device__ __forceinline__ float tanha(float x) {
    float r;
    asm("tanh.approx.f32 %0, %1;" : "=f"(r) : "f"(x));
    return r;
}
// sigmoid(x) = 0.5*tanh(0.5x) + 0.5 : 1 MUFU + 2 FMA
__device__ __forceinline__ float sigf(float x) {
    return fmaf(0.5f, tanha(0.5f * x), 0.5f);
}
__device__ __forceinline__ float tanhfast(float x) {
    return tanha(x);
}

__global__ void __launch_bounds__(TPB, 1)
bilstm_kernel(const float* __restrict__ rain_hist,
              const float* __restrict__ feature,
              const float* __restrict__ h0,
              const float* __restrict__ c0,
              const float* __restrict__ W_mlp,
              const float* __restrict__ b_mlp,
              const float* __restrict__ Wih_g,
              const float* __restrict__ Whh_g,
              const float* __restrict__ b_ih_g,
              const float* __restrict__ b_hh_g,
              const float* __restrict__ Wih0,
              const float* __restrict__ Whh0,
              const float* __restrict__ b0,
              const float* __restrict__ Wih1,
              const float* __restrict__ Whh1,
              const float* __restrict__ b1,
              const float* __restrict__ W_fc,
              const float* __restrict__ b_fc,
              float* __restrict__ out)
{
    extern __shared__ float sm[];
    float* sX   = sm + OFF_X;
    float* sXin = sm + OFF_XIN;
    float* sG   = sm + OFF_G;
    float* sH   = sm + OFF_H;
    float* sCst = sm + OFF_C;
    float* sXN  = sm + OFF_XN;
    float* sGX  = sm + OFF_GX;
    float* sGH  = sm + OFF_GH;
    float* sU   = sm + OFF_U;
    float* sY1  = sm + OFF_Y1;

    const int tid = threadIdx.x;
    const int cta = blockIdx.x;
    const int bg  = cta * BT;

    const int dirg = tid >> 7;   // gate-phase: direction
    const int jg   = tid & 127;  // gate-phase: gate row
    const int bu   = (tid >> 5) & 3;  // update-phase: batch
    const int ju   = tid & 31;        // update-phase: hidden index
    const int row  = dirg * 128 + jg; // gate row id (per dir)

    // ---- per-thread weight rows in REGISTERS (fully unrolled -> no dyn idx) ----
    float w0x[DD], w0h[HH], bias0;
    float w1x[64], w1h[HH], bias1;
#pragma unroll
    for (int k = 0; k < DD; ++k) w0x[k] = Wih0[row * DD + k];
#pragma unroll
    for (int k = 0; k < HH; ++k) w0h[k] = Whh0[row * HH + k];
    bias0 = b0[row];
#pragma unroll
    for (int k = 0; k < 64; ++k) w1x[k] = Wih1[row * 64 + k];
#pragma unroll
    for (int k = 0; k < HH; ++k) w1h[k] = Whh1[row * HH + k];
    bias1 = b1[row];

    // ---- initial states ----
    for (int e = tid; e < 4 * HH * BT; e += TPB) {
        int ld = e >> 7, k = (e >> 2) & 31, b = e & 3;
        sH[(ld * HH + k) * BT + b]   = h0[((size_t)ld * NB + bg + b) * HH + k];
        sCst[(ld * HH + k) * BT + b] = c0[((size_t)ld * NB + bg + b) * HH + k];
    }
    for (int e = tid; e < NC * BT; e += TPB) {
        int c = e >> 2, b = e & 3;
        sXN[c * BT + b] = rain_hist[((size_t)(bg + b) * NHIST + (NHIST - 1)) * NC + c];
    }
    __syncthreads();

    for (int t = 0; t < NPRED; ++t) {
        // ============ Phase 1: build x tile (slot0=g later, slot1=xn, 2..14=feat) ============
        for (int e = tid; e < NC * NFEAT * BT; e += TPB) {
            int b = e / (NC * NFEAT);
            int rem = e - b * (NC * NFEAT);
            int c = rem / NFEAT;
            int kk = rem - c * NFEAT;
            sX[(c * DD + 2 + kk) * BT + b] =
                feature[(((size_t)(bg + b) * FTOT + NHIST + t) * NC + c) * NFEAT + kk];
        }
        for (int e = tid; e < NC * BT; e += TPB) {
            int c = e >> 2, b = e & 3;
            sX[(c * DD + 1) * BT + b] = sXN[c * BT + b];
        }
        __syncthreads();

        // ============ Phase 2: gated graph MLP (4-way c-split chains) ============
        if (tid < NC) {
            const int j = tid;
            u64 A0 = pk2(b_mlp[j]), A1 = 0, A2 = 0, A3 = 0;
            u64 B0 = A0, B1 = 0, B2 = 0, B3 = 0;
            const float* wbase = W_mlp + j;
            for (int c = 0; c < NC; c += 4) {
#pragma unroll
                for (int p = 0; p < 4; ++p) {
                    const ulonglong2* xp = (const ulonglong2*)(sX + ((c + p) * DD + 1) * BT);
                    const float* wp = wbase + (size_t)(c + p) * IND * NC;
#pragma unroll
                    for (int kk = 0; kk < IND; ++kk) {
                        u64 w = pk2(wp[(size_t)kk * NC]);
                        ulonglong2 xv = xp[kk];
                        if (p == 0) { ffma2(A0, xv.x, w); ffma2(B0, xv.y, w); }
                        if (p == 1) { ffma2(A1, xv.x, w); ffma2(B1, xv.y, w); }
                        if (p == 2) { ffma2(A2, xv.x, w); ffma2(B2, xv.y, w); }
                        if (p == 3) { ffma2(A3, xv.x, w); ffma2(B3, xv.y, w); }
                    }
                }
            }
            float2 v01 = unpk(addx2(addx2(A0, A1), addx2(A2, A3)));
            float2 v23 = unpk(addx2(addx2(B0, B1), addx2(B2, B3)));
            sX[(j * DD) * BT + 0] = sigf(v01.x);
            sX[(j * DD) * BT + 1] = sigf(v01.y);
            sX[(j * DD) * BT + 2] = sigf(v23.x);
            sX[(j * DD) * BT + 3] = sigf(v23.y);
        }
        __syncthreads();

        // ============ Phase 3: GRU cell ============
        for (int e = tid; e < BT * DD; e += TPB) {
            int b = e / DD, k = e - b * DD;
            float s = 0.0f;
            for (int c = 0; c < NC; ++c) s += sX[(c * DD + k) * BT + b];
            sU[b * 16 + k] = s * (1.0f / NC);
        }
        __syncthreads();
        for (int e = tid; e < BT * 96; e += TPB) {
            int b = e / 96, j = e - b * 96;
            float a = b_ih_g[j];
#pragma unroll
            for (int k = 0; k < DD; ++k)
                a = fmaf(sU[b * 16 + k], Wih_g[k * 96 + j], a);
            sGX[e] = a;
        }
        for (int e = tid; e < 16 * 96; e += TPB) {
            int lb = e / 96, j = e - lb * 96;
            int l = lb >> 2, b = lb & 3;
            float a = b_hh_g[j];
#pragma unroll
            for (int k = 0; k < HH; ++k)
                a = fmaf(sH[(l * HH + k) * BT + b], Whh_g[k * 96 + j], a);
            sGH[e] = a;
        }
        __syncthreads();
        for (int e = tid; e < 4 * BT * HH; e += TPB) {
            int l = e >> 7, b = (e >> 5) & 3, j = e & 31;
            int gb = b * 96, ghb = (l * BT + b) * 96;
            float r = sigf(sGX[gb + j]      + sGH[ghb + j]);
            float z = sigf(sGX[gb + 32 + j] + sGH[ghb + 32 + j]);
            float n = tanhfast(sGX[gb + 64 + j] + r * sGH[ghb + 64 + j]);
            int hi = (l * HH + j) * BT + b;
            sH[hi] = (1.0f - z) * n + z * sH[hi];
        }
        __syncthreads();

        // ============ Phase 4: BiLSTM layer 0 over cities ============
        {
            const ulonglong2* hp = (const ulonglong2*)(sH + dirg * HH * BT);
            for (int s = 0; s < NC; ++s) {
                const int city = dirg ? (NC - 1 - s) : s;
                const ulonglong2* xp = (const ulonglong2*)(sX + city * DD * BT);
                u64 a01 = pk2(bias0), a23 = a01;
#pragma unroll
                for (int k = 0; k < DD; ++k) {
                    u64 w = pk2(w0x[k]);
                    ulonglong2 xv = xp[k];
                    ffma2(a01, xv.x, w); ffma2(a23, xv.y, w);
                }
#pragma unroll
                for (int k = 0; k < HH; ++k) {
                    u64 w = pk2(w0h[k]);
                    ulonglong2 hv = hp[k];
                    ffma2(a01, hv.x, w); ffma2(a23, hv.y, w);
                }
                float2 v01 = unpk(a01), v23 = unpk(a23);
                float* gp = sG + dirg * 512 + jg;
                gp[0] = v01.x; gp[128] = v01.y; gp[256] = v23.x; gp[384] = v23.y;
                __syncthreads();
                {
                    const int du = tid >> 7;
                    const int cityu = du ? (NC - 1 - s) : s;
                    const float* g = sG + du * 512 + bu * 128;
                    float iv = sigf(g[ju]);
                    float fv = sigf(g[32 + ju]);
                    float gv = tanhfast(g[64 + ju]);
                    float ov = sigf(g[96 + ju]);
                    int ci = (du * HH + ju) * BT + bu;
                    float cc = fmaf(fv, sCst[ci], iv * gv);
                    sCst[ci] = cc;
                    float hh2 = ov * tanhfast(cc);
                    sH[ci] = hh2;
                    g_y0[((size_t)(cta * NC + cityu) * BT + bu) * 64 + du * 32 + ju] = hh2;
                }
                __syncthreads();
            }
        }

        // ============ Phase 5: BiLSTM layer 1 over cities (prefetched, dbl-buffered) ============
        {
            // stage s = 0 into buffer 0
            {
#pragma unroll
                for (int q = 0; q < 2; ++q) {
                    int e = tid * 2 + q;
                    int ci = e >> 8, r = e & 255, k = r >> 2, b = r & 3;
                    int city = ci ? (NC - 1) : 0;
                    sXin[e] = g_y0[((size_t)(cta * NC + city) * BT + b) * 64 + k];
                }
            }
            __syncthreads();
            int buf = 0;
            const ulonglong2* hp = (const ulonglong2*)(sH + (2 + dirg) * HH * BT);
            for (int s = 0; s < NC; ++s) {
                // issue prefetch for s+1 early (clamped at the end)
                float pf0, pf1;
                {
                    const int sp = (s + 1 < NC) ? (s + 1) : s;
                    int e = tid * 2;
                    int ci = e >> 8, r = e & 255, k = r >> 2, b = r & 3;
                    int city = ci ? (NC - 1 - sp) : sp;
                    pf0 = g_y0[((size_t)(cta * NC + city) * BT + b) * 64 + k];
                    e = tid * 2 + 1;
                    ci = e >> 8; r = e & 255; k = r >> 2; b = r & 3;
                    city = ci ? (NC - 1 - sp) : sp;
                    pf1 = g_y0[((size_t)(cta * NC + city) * BT + b) * 64 + k];
                }
                // gates
                const ulonglong2* xp = (const ulonglong2*)(sXin + buf * 512 + dirg * 256);
                u64 a01 = pk2(bias1), a23 = a01;
#pragma unroll
                for (int k = 0; k < 64; ++k) {
                    u64 w = pk2(w1x[k]);
                    ulonglong2 xv = xp[k];
                    ffma2(a01, xv.x, w); ffma2(a23, xv.y, w);
                }
#pragma unroll
                for (int k = 0; k < HH; ++k) {
                    u64 w = pk2(w1h[k]);
                    ulonglong2 hv = hp[k];
                    ffma2(a01, hv.x, w); ffma2(a23, hv.y, w);
                }
                float2 v01 = unpk(a01), v23 = unpk(a23);
                float* gp = sG + dirg * 512 + jg;
                gp[0] = v01.x; gp[128] = v01.y; gp[256] = v23.x; gp[384] = v23.y;
                __syncthreads();
                // stash prefetched next-city input into the other buffer
                *(float2*)(sXin + (buf ^ 1) * 512 + tid * 2) = make_float2(pf0, pf1);
                // update
                {
                    const int du = tid >> 7;
                    const float* g = sG + du * 512 + bu * 128;
                    float iv = sigf(g[ju]);
                    float fv = sigf(g[32 + ju]);
                    float gv = tanhfast(g[64 + ju]);
                    float ov = sigf(g[96 + ju]);
                    int ci = ((2 + du) * HH + ju) * BT + bu;
                    float cc = fmaf(fv, sCst[ci], iv * gv);
                    sCst[ci] = cc;
                    float hh2 = ov * tanhfast(cc);
                    sH[ci] = hh2;
                    if (du == 0)  // only forward half of y1 is consumed
                        sY1[(s * BT + bu) * 32 + ju] = hh2;
                }
                __syncthreads();
                buf ^= 1;
            }
        }

        // ============ Phase 6: FC head -> xn, write output ============
        {
            const float bfc = b_fc[0];
            for (int e = tid; e < NC * BT; e += TPB) {
                int c = e >> 2, b = e & 3;
                float a = bfc;
                const float* yp = sY1 + (c * BT + b) * 32;
#pragma unroll
                for (int j = 0; j < HH; ++j)
                    a = fmaf(yp[j], W_fc[j], a);
                sXN[c * BT + b] = a;
                out[((size_t)(bg + b) * NPRED + t) * NC + c] = a;
            }
        }
        __syncthreads();
    }
}

extern "C" void kernel_launch(void* const* d_in, const int* in_sizes, int n_in,
                              void* d_out, int out_size) {
    (void)in_sizes; (void)n_in; (void)out_size;
    const float* rain_hist = (const float*)d_in[0];
    const float* feature   = (const float*)d_in[1];
    const float* h0        = (const float*)d_in[2];
    const float* c0        = (const float*)d_in[3];
    const float* W_mlp     = (const float*)d_in[4];
    const float* b_mlp     = (const float*)d_in[5];
    const float* Wih_g     = (const float*)d_in[6];
    const float* Whh_g     = (const float*)d_in[7];
    const float* b_ih_g    = (const float*)d_in[8];
    const float* b_hh_g    = (const float*)d_in[9];
    const float* Wih0      = (const float*)d_in[10];
    const float* Whh0      = (const float*)d_in[11];
    const float* b0        = (const float*)d_in[12];
    const float* Wih1      = (const float*)d_in[13];
    const float* Whh1      = (const float*)d_in[14];
    const float* b1        = (const float*)d_in[15];
    const float* W_fc      = (const float*)d_in[16];
    const float* b_fc      = (const float*)d_in[17];

    size_t smem = (size_t)SMEM_FLOATS * sizeof(float);
    cudaFuncSetAttribute(bilstm_kernel,
                         cudaFuncAttributeMaxDynamicSharedMemorySize, (int)smem);

    bilstm_kernel<<<NCTA, TPB, smem>>>(
        rain_hist, feature, h0, c0, W_mlp, b_mlp,
        Wih_g, Whh_g, b_ih_g, b_hh_g,
        Wih0, Whh0, b0, Wih1, Whh1, b1,
        W_fc, b_fc, (float*)d_out);
}